// round 2
// baseline (speedup 1.0000x reference)
#include <cuda_runtime.h>

// Problem constants
#define KB_  2
#define KS_  2048
#define KD_  1024
#define KH_  16
#define KHD_ 64
#define KM_  (KB_ * KS_)   // 4096 rows

// Scratch (allocation-free rule: __device__ globals)
__device__ float g_q[(size_t)KM_ * KD_];
__device__ float g_k[(size_t)KM_ * KD_];
__device__ float g_v[(size_t)KM_ * KD_];
__device__ float g_att[(size_t)KM_ * KD_];

// ---------------------------------------------------------------------------
// Tiled fp32 GEMM: C[M,N] = A[M,K] @ W[K,N] + bias[N]
// BM=128, BN=128, BK=16, 256 threads, 8x8 per-thread microtile
// ---------------------------------------------------------------------------
__global__ __launch_bounds__(256) void sgemm_bias(
    const float* __restrict__ A, const float* __restrict__ W,
    const float* __restrict__ bias, float* __restrict__ C,
    int M, int N, int K)
{
    constexpr int BM = 128, BN = 128, BK = 16;
    __shared__ float As[BK][BM + 4];   // transposed A tile: As[k][m]
    __shared__ float Bs[BK][BN + 4];   // Bs[k][n]

    const int tid = threadIdx.x;
    const int tx = tid & 15;          // 0..15 -> N
    const int ty = tid >> 4;          // 0..15 -> M
    const int bm = blockIdx.y * BM;
    const int bn = blockIdx.x * BN;

    float acc[8][8];
#pragma unroll
    for (int i = 0; i < 8; i++)
#pragma unroll
        for (int j = 0; j < 8; j++) acc[i][j] = 0.f;

    for (int k0 = 0; k0 < K; k0 += BK) {
        // Load A tile (128x16) transposed into smem
#pragma unroll
        for (int i = 0; i < 2; i++) {
            int idx = tid + i * 256;          // 0..511 float4 slots
            int r  = idx >> 2;                // 0..127 (row within tile)
            int c4 = (idx & 3) * 4;           // 0,4,8,12
            float4 v = *(const float4*)(A + (size_t)(bm + r) * K + k0 + c4);
            As[c4 + 0][r] = v.x;
            As[c4 + 1][r] = v.y;
            As[c4 + 2][r] = v.z;
            As[c4 + 3][r] = v.w;
        }
        // Load B tile (16x128)
#pragma unroll
        for (int i = 0; i < 2; i++) {
            int idx = tid + i * 256;
            int r  = idx >> 5;                // 0..15
            int c4 = (idx & 31) * 4;          // 0..124
            *(float4*)&Bs[r][c4] = *(const float4*)(W + (size_t)(k0 + r) * N + bn + c4);
        }
        __syncthreads();

#pragma unroll
        for (int k = 0; k < BK; k++) {
            float a[8], b[8];
            *(float4*)&a[0] = *(const float4*)&As[k][ty * 8];
            *(float4*)&a[4] = *(const float4*)&As[k][ty * 8 + 4];
            *(float4*)&b[0] = *(const float4*)&Bs[k][tx * 8];
            *(float4*)&b[4] = *(const float4*)&Bs[k][tx * 8 + 4];
#pragma unroll
            for (int i = 0; i < 8; i++)
#pragma unroll
                for (int j = 0; j < 8; j++)
                    acc[i][j] += a[i] * b[j];
        }
        __syncthreads();
    }

#pragma unroll
    for (int i = 0; i < 8; i++) {
        int row = bm + ty * 8 + i;
#pragma unroll
        for (int j = 0; j < 8; j += 4) {
            int col = bn + tx * 8 + j;
            float4 o;
            o.x = acc[i][j + 0] + bias[col + 0];
            o.y = acc[i][j + 1] + bias[col + 1];
            o.z = acc[i][j + 2] + bias[col + 2];
            o.w = acc[i][j + 3] + bias[col + 3];
            *(float4*)(C + (size_t)row * N + col) = o;
        }
    }
}

// ---------------------------------------------------------------------------
// Flash attention (causal), fp32. One block per (q-tile, head, batch).
// BQ=BK=64, HD=64. 256 threads as 16x16, 4x4 microtiles for S and O.
// ---------------------------------------------------------------------------
#define FA_STR 68   // 64 + 4 padding (keeps float4 alignment)

__global__ __launch_bounds__(256) void flash_attn(
    const float* __restrict__ Q, const float* __restrict__ K,
    const float* __restrict__ V, float* __restrict__ O)
{
    constexpr int BQ = 64, BK = 64, HD = 64;
    extern __shared__ float sm[];
    float* Qs   = sm;                      // [HD][FA_STR]  transposed: Qs[d*STR + row]
    float* Ks   = Qs + HD * FA_STR;        // [HD][FA_STR]  transposed: Ks[d*STR + col]
    float* Vs   = Ks + HD * FA_STR;        // [BK][HD]      row-major:  Vs[j*HD + d]
    float* Ps   = Vs + BK * HD;            // [BK][FA_STR]  transposed: Ps[j*STR + row]
    float* redm = Ps + BK * FA_STR;        // [BQ][17]
    float* reds = redm + BQ * 17;          // [BQ][17]

    const int tid = threadIdx.x;
    const int tx = tid & 15;               // cols (keys / head-dims)
    const int ty = tid >> 4;               // rows (queries)
    const int qt = blockIdx.x;
    const int h  = blockIdx.y;
    const int b  = blockIdx.z;
    const int q0 = qt * BQ;

    const float* Qb = Q + (size_t)b * KS_ * KD_ + (size_t)h * KHD_;
    const float* Kb = K + (size_t)b * KS_ * KD_ + (size_t)h * KHD_;
    const float* Vb = V + (size_t)b * KS_ * KD_ + (size_t)h * KHD_;

    // Load Q tile (64 rows x 64 dims), store transposed
#pragma unroll
    for (int i = 0; i < 4; i++) {
        int idx = tid + i * 256;           // 0..1023 float4 slots
        int row = idx >> 4;                // 0..63
        int d4  = (idx & 15) * 4;          // 0..60
        float4 v4 = *(const float4*)(Qb + (size_t)(q0 + row) * KD_ + d4);
        Qs[(d4 + 0) * FA_STR + row] = v4.x;
        Qs[(d4 + 1) * FA_STR + row] = v4.y;
        Qs[(d4 + 2) * FA_STR + row] = v4.z;
        Qs[(d4 + 3) * FA_STR + row] = v4.w;
    }

    float o[4][4];
#pragma unroll
    for (int i = 0; i < 4; i++)
#pragma unroll
        for (int j = 0; j < 4; j++) o[i][j] = 0.f;
    float mrow[4] = {-1e30f, -1e30f, -1e30f, -1e30f};
    float lrow[4] = {0.f, 0.f, 0.f, 0.f};

    const float scale = 0.125f;            // 1/sqrt(64)

    for (int kt = 0; kt <= qt; kt++) {
        const int k0 = kt * BK;
        // Load K (transposed) and V (row-major) tiles
#pragma unroll
        for (int i = 0; i < 4; i++) {
            int idx = tid + i * 256;
            int row = idx >> 4;
            int d4  = (idx & 15) * 4;
            float4 kv = *(const float4*)(Kb + (size_t)(k0 + row) * KD_ + d4);
            Ks[(d4 + 0) * FA_STR + row] = kv.x;
            Ks[(d4 + 1) * FA_STR + row] = kv.y;
            Ks[(d4 + 2) * FA_STR + row] = kv.z;
            Ks[(d4 + 3) * FA_STR + row] = kv.w;
            float4 vv = *(const float4*)(Vb + (size_t)(k0 + row) * KD_ + d4);
            *(float4*)(Vs + row * HD + d4) = vv;
        }
        __syncthreads();

        // S = Q K^T  (4x4 per thread)
        float s[4][4];
#pragma unroll
        for (int i = 0; i < 4; i++)
#pragma unroll
            for (int j = 0; j < 4; j++) s[i][j] = 0.f;
#pragma unroll 16
        for (int d = 0; d < HD; d++) {
            float a[4], bb[4];
            *(float4*)a  = *(const float4*)(Qs + d * FA_STR + ty * 4);
            *(float4*)bb = *(const float4*)(Ks + d * FA_STR + tx * 4);
#pragma unroll
            for (int i = 0; i < 4; i++)
#pragma unroll
                for (int j = 0; j < 4; j++)
                    s[i][j] += a[i] * bb[j];
        }

        // scale + causal mask (only the diagonal tile needs masking)
        const bool diag = (kt == qt);
#pragma unroll
        for (int i = 0; i < 4; i++)
#pragma unroll
            for (int j = 0; j < 4; j++) {
                float val = s[i][j] * scale;
                if (diag && (tx * 4 + j) > (ty * 4 + i)) val = -1e30f;
                s[i][j] = val;
            }

        // Row max partials
#pragma unroll
        for (int i = 0; i < 4; i++) {
            float m = fmaxf(fmaxf(s[i][0], s[i][1]), fmaxf(s[i][2], s[i][3]));
            redm[(ty * 4 + i) * 17 + tx] = m;
        }
        __syncthreads();

        float mnew[4], fac[4];
#pragma unroll
        for (int i = 0; i < 4; i++) {
            float m = mrow[i];
#pragma unroll
            for (int t = 0; t < 16; t++)
                m = fmaxf(m, redm[(ty * 4 + i) * 17 + t]);
            mnew[i] = m;
            fac[i]  = __expf(mrow[i] - m);
            mrow[i] = m;
        }

        // P = exp(S - m), partial sums, store P transposed, rescale O
#pragma unroll
        for (int i = 0; i < 4; i++) {
            float psum = 0.f;
#pragma unroll
            for (int j = 0; j < 4; j++) {
                float p = __expf(s[i][j] - mnew[i]);
                psum += p;
                Ps[(tx * 4 + j) * FA_STR + ty * 4 + i] = p;
            }
            reds[(ty * 4 + i) * 17 + tx] = psum;
            lrow[i] *= fac[i];
#pragma unroll
            for (int j = 0; j < 4; j++) o[i][j] *= fac[i];
        }
        __syncthreads();

#pragma unroll
        for (int i = 0; i < 4; i++) {
            float sum = 0.f;
#pragma unroll
            for (int t = 0; t < 16; t++)
                sum += reds[(ty * 4 + i) * 17 + t];
            lrow[i] += sum;
        }

        // O += P V  (4 rows x 4 dims per thread)
#pragma unroll 16
        for (int j = 0; j < BK; j++) {
            float pa[4], va[4];
            *(float4*)pa = *(const float4*)(Ps + j * FA_STR + ty * 4);
            *(float4*)va = *(const float4*)(Vs + j * HD + tx * 4);
#pragma unroll
            for (int i = 0; i < 4; i++)
#pragma unroll
                for (int jj = 0; jj < 4; jj++)
                    o[i][jj] += pa[i] * va[jj];
        }
        __syncthreads();
    }

    // Epilogue: normalize and write (B,S,D) layout
    float* Ob = O + (size_t)b * KS_ * KD_ + (size_t)h * KHD_;
#pragma unroll
    for (int i = 0; i < 4; i++) {
        int row = q0 + ty * 4 + i;
        float inv = 1.f / lrow[i];
        float4 out;
        out.x = o[i][0] * inv;
        out.y = o[i][1] * inv;
        out.z = o[i][2] * inv;
        out.w = o[i][3] * inv;
        *(float4*)(Ob + (size_t)row * KD_ + tx * 4) = out;
    }
}

// ---------------------------------------------------------------------------
// Launch
// ---------------------------------------------------------------------------
extern "C" void kernel_launch(void* const* d_in, const int* in_sizes, int n_in,
                              void* d_out, int out_size)
{
    (void)in_sizes; (void)n_in; (void)out_size;
    const float* x  = (const float*)d_in[0];
    const float* Wq = (const float*)d_in[1];
    const float* bq = (const float*)d_in[2];
    const float* Wk = (const float*)d_in[3];
    const float* bk = (const float*)d_in[4];
    const float* Wv = (const float*)d_in[5];
    const float* bv = (const float*)d_in[6];
    const float* Wo = (const float*)d_in[7];
    const float* bo = (const float*)d_in[8];
    // d_in[9] = mask: always causal tril -> handled analytically
    float* out = (float*)d_out;

    float *q, *k, *v, *att;
    cudaGetSymbolAddress((void**)&q,   g_q);
    cudaGetSymbolAddress((void**)&k,   g_k);
    cudaGetSymbolAddress((void**)&v,   g_v);
    cudaGetSymbolAddress((void**)&att, g_att);

    const int fa_smem = (64 * FA_STR * 3 + 64 * 64 + 2 * 64 * 17) * (int)sizeof(float);
    cudaFuncSetAttribute(flash_attn, cudaFuncAttributeMaxDynamicSharedMemorySize, fa_smem);

    dim3 gemmGrid(KD_ / 128, KM_ / 128);   // (8, 32)
    sgemm_bias<<<gemmGrid, 256>>>(x, Wq, bq, q, KM_, KD_, KD_);
    sgemm_bias<<<gemmGrid, 256>>>(x, Wk, bk, k, KM_, KD_, KD_);
    sgemm_bias<<<gemmGrid, 256>>>(x, Wv, bv, v, KM_, KD_, KD_);

    dim3 faGrid(KS_ / 64, KH_, KB_);       // (32, 16, 2)
    flash_attn<<<faGrid, 256, fa_smem>>>(q, k, v, att);

    sgemm_bias<<<gemmGrid, 256>>>(att, Wo, bo, out, KM_, KD_, KD_);
}

// round 4
// speedup vs baseline: 1.5035x; 1.5035x over previous
#include <cuda_runtime.h>
#include <cstdint>

// Problem constants
#define KB_  2
#define KS_  2048
#define KD_  1024
#define KH_  16
#define KHD_ 64
#define KM_  (KB_ * KS_)   // 4096 rows

// Scratch (allocation-free rule: __device__ globals)
__device__ float g_q[(size_t)KM_ * KD_];
__device__ float g_k[(size_t)KM_ * KD_];
__device__ float g_v[(size_t)KM_ * KD_];
__device__ float g_att[(size_t)KM_ * KD_];

// ===========================================================================
// Helpers
// ===========================================================================
__device__ __forceinline__ void cpa16(uint32_t dst, const float* src) {
    asm volatile("cp.async.cg.shared.global [%0], [%1], 16;"
                 :: "r"(dst), "l"(src));
}
template <int N>
__device__ __forceinline__ void cpwait() {
    asm volatile("cp.async.wait_group %0;" :: "n"(N) : "memory");
}
__device__ __forceinline__ uint32_t s2u(const void* p) {
    uint32_t a;
    asm("{ .reg .u64 t; cvta.to.shared.u64 t, %1; cvt.u32.u64 %0, t; }"
        : "=r"(a) : "l"(p));
    return a;
}
__device__ __forceinline__ uint32_t f2tf32(float f) {
    uint32_t u;
    asm("cvt.rna.tf32.f32 %0, %1;" : "=r"(u) : "f"(f));
    return u;
}
// D += A(16x8) * B(8x8), tf32 inputs, fp32 accumulate
__device__ __forceinline__ void mma_tf32(float* c, const uint32_t* a, const uint32_t* b) {
    asm volatile(
        "mma.sync.aligned.m16n8k8.row.col.f32.tf32.tf32.f32 "
        "{%0,%1,%2,%3}, {%4,%5,%6,%7}, {%8,%9}, {%0,%1,%2,%3};"
        : "+f"(c[0]), "+f"(c[1]), "+f"(c[2]), "+f"(c[3])
        : "r"(a[0]), "r"(a[1]), "r"(a[2]), "r"(a[3]), "r"(b[0]), "r"(b[1]));
}

// ===========================================================================
// tf32 mma.sync GEMM: C[M,N] = A[M,K] @ W[K,N] + bias,  M=4096, N=K=1024
// CTA tile 128x128x32, 256 thr (8 warps, 2x4 layout, 64x32 warp tile),
// 3-stage cp.async pipeline.
// ===========================================================================
#define GBM 128
#define GBN 128
#define GBK 32
#define GST 3
#define GNC (KD_ / GBK)        // 32 K-chunks
#define ASTR 36                // A smem row stride (floats)
#define BSTR 136               // B smem row stride (floats)
#define ASLOT (GBM * ASTR)     // 4608 floats
#define BSLOT (GBK * BSTR)     // 4352 floats

__device__ __forceinline__ void g_load_chunk(
    const float* __restrict__ Ag, const float* __restrict__ Wg,
    uint32_t as, uint32_t bs, int tid)
{
    // A: 128 rows x 32 floats (8 float4/row) = 1024 float4
#pragma unroll
    for (int i = 0; i < 4; i++) {
        int idx = tid + i * 256;
        int r = idx >> 3, c4 = (idx & 7) * 4;
        cpa16(as + (uint32_t)(r * ASTR + c4) * 4, Ag + (size_t)r * KD_ + c4);
    }
    // B (= W K-major): 32 rows x 128 floats = 1024 float4
#pragma unroll
    for (int i = 0; i < 4; i++) {
        int idx = tid + i * 256;
        int r = idx >> 5, c4 = (idx & 31) * 4;
        cpa16(bs + (uint32_t)(r * BSTR + c4) * 4, Wg + (size_t)r * KD_ + c4);
    }
    asm volatile("cp.async.commit_group;" ::: "memory");
}

__global__ __launch_bounds__(256, 2) void gemm_tf32(
    const float* __restrict__ A, const float* __restrict__ W,
    const float* __restrict__ bias, float* __restrict__ C)
{
    extern __shared__ float smem[];
    float* As = smem;                    // [GST][ASLOT]
    float* Bs = smem + GST * ASLOT;      // [GST][BSLOT]
    const uint32_t as_u = s2u(As);
    const uint32_t bs_u = s2u(Bs);

    const int tid  = threadIdx.x;
    const int wid  = tid >> 5, lane = tid & 31;
    const int wm   = wid >> 2;           // 0..1  (rows, 64 each)
    const int wn   = wid & 3;            // 0..3  (cols, 32 each)
    const int gid  = lane >> 2;          // 0..7
    const int tig  = lane & 3;           // 0..3
    const int bm   = blockIdx.y * GBM;
    const int bn   = blockIdx.x * GBN;

    const float* Abase = A + (size_t)bm * KD_;
    const float* Wbase = W + bn;

    float acc[4][4][4];                  // [mt][nt][4]
#pragma unroll
    for (int mt = 0; mt < 4; mt++)
#pragma unroll
        for (int nt = 0; nt < 4; nt++)
#pragma unroll
            for (int r = 0; r < 4; r++) acc[mt][nt][r] = 0.f;

    // Prologue: 2 chunks in flight
    g_load_chunk(Abase, Wbase, as_u, bs_u, tid);
    g_load_chunk(Abase + GBK, Wbase + (size_t)GBK * KD_,
                 as_u + ASLOT * 4, bs_u + BSLOT * 4, tid);

    for (int kc = 0; kc < GNC; kc++) {
        if (kc == GNC - 1) cpwait<0>(); else cpwait<1>();
        __syncthreads();

        // Prefetch chunk kc+2 into slot (kc+2)%3 (freed at iter kc-1)
        const int kn = kc + 2;
        if (kn < GNC) {
            const int sl = kn % GST;
            g_load_chunk(Abase + kn * GBK, Wbase + (size_t)(kn * GBK) * KD_,
                         as_u + (uint32_t)sl * ASLOT * 4,
                         bs_u + (uint32_t)sl * BSLOT * 4, tid);
        }

        // Compute chunk kc from slot kc%3
        const float* Ac = As + (kc % GST) * ASLOT;
        const float* Bc = Bs + (kc % GST) * BSLOT;
#pragma unroll
        for (int ks = 0; ks < 4; ks++) {
            const int k0 = ks * 8;
            uint32_t af[4][4], bf[4][2];
#pragma unroll
            for (int mt = 0; mt < 4; mt++) {
                const int r0 = wm * 64 + mt * 16 + gid;
                af[mt][0] = f2tf32(Ac[r0 * ASTR + k0 + tig]);
                af[mt][1] = f2tf32(Ac[(r0 + 8) * ASTR + k0 + tig]);
                af[mt][2] = f2tf32(Ac[r0 * ASTR + k0 + tig + 4]);
                af[mt][3] = f2tf32(Ac[(r0 + 8) * ASTR + k0 + tig + 4]);
            }
#pragma unroll
            for (int nt = 0; nt < 4; nt++) {
                const int n0 = wn * 32 + nt * 8 + gid;
                bf[nt][0] = f2tf32(Bc[(k0 + tig) * BSTR + n0]);
                bf[nt][1] = f2tf32(Bc[(k0 + tig + 4) * BSTR + n0]);
            }
#pragma unroll
            for (int mt = 0; mt < 4; mt++)
#pragma unroll
                for (int nt = 0; nt < 4; nt++)
                    mma_tf32(acc[mt][nt], af[mt], bf[nt]);
        }
        __syncthreads();
    }

    // Epilogue: bias add + store (float2, coalesced across tig)
#pragma unroll
    for (int mt = 0; mt < 4; mt++) {
        const int r0 = bm + wm * 64 + mt * 16 + gid;
#pragma unroll
        for (int nt = 0; nt < 4; nt++) {
            const int col = bn + wn * 32 + nt * 8 + 2 * tig;
            const float b0 = bias[col], b1 = bias[col + 1];
            float2 v0 = make_float2(acc[mt][nt][0] + b0, acc[mt][nt][1] + b1);
            float2 v1 = make_float2(acc[mt][nt][2] + b0, acc[mt][nt][3] + b1);
            *(float2*)(C + (size_t)r0 * KD_ + col)       = v0;
            *(float2*)(C + (size_t)(r0 + 8) * KD_ + col) = v1;
        }
    }
}

// ---------------------------------------------------------------------------
// Flash attention (causal), fp32 — unchanged (725us; round-5 target).
// ---------------------------------------------------------------------------
#define FA_STR 68

__global__ __launch_bounds__(256) void flash_attn(
    const float* __restrict__ Q, const float* __restrict__ K,
    const float* __restrict__ V, float* __restrict__ O)
{
    constexpr int BQ = 64, BK = 64, HD = 64;
    extern __shared__ float sm[];
    float* Qs   = sm;
    float* Ks   = Qs + HD * FA_STR;
    float* Vs   = Ks + HD * FA_STR;
    float* Ps   = Vs + BK * HD;
    float* redm = Ps + BK * FA_STR;
    float* reds = redm + BQ * 17;

    const int tid = threadIdx.x;
    const int tx = tid & 15;
    const int ty = tid >> 4;
    const int qt = blockIdx.x;
    const int h  = blockIdx.y;
    const int b  = blockIdx.z;
    const int q0 = qt * BQ;

    const float* Qb = Q + (size_t)b * KS_ * KD_ + (size_t)h * KHD_;
    const float* Kb = K + (size_t)b * KS_ * KD_ + (size_t)h * KHD_;
    const float* Vb = V + (size_t)b * KS_ * KD_ + (size_t)h * KHD_;

#pragma unroll
    for (int i = 0; i < 4; i++) {
        int idx = tid + i * 256;
        int row = idx >> 4;
        int d4  = (idx & 15) * 4;
        float4 v4 = *(const float4*)(Qb + (size_t)(q0 + row) * KD_ + d4);
        Qs[(d4 + 0) * FA_STR + row] = v4.x;
        Qs[(d4 + 1) * FA_STR + row] = v4.y;
        Qs[(d4 + 2) * FA_STR + row] = v4.z;
        Qs[(d4 + 3) * FA_STR + row] = v4.w;
    }

    float o[4][4];
#pragma unroll
    for (int i = 0; i < 4; i++)
#pragma unroll
        for (int j = 0; j < 4; j++) o[i][j] = 0.f;
    float mrow[4] = {-1e30f, -1e30f, -1e30f, -1e30f};
    float lrow[4] = {0.f, 0.f, 0.f, 0.f};

    const float scale = 0.125f;

    for (int kt = 0; kt <= qt; kt++) {
        const int k0 = kt * BK;
#pragma unroll
        for (int i = 0; i < 4; i++) {
            int idx = tid + i * 256;
            int row = idx >> 4;
            int d4  = (idx & 15) * 4;
            float4 kv = *(const float4*)(Kb + (size_t)(k0 + row) * KD_ + d4);
            Ks[(d4 + 0) * FA_STR + row] = kv.x;
            Ks[(d4 + 1) * FA_STR + row] = kv.y;
            Ks[(d4 + 2) * FA_STR + row] = kv.z;
            Ks[(d4 + 3) * FA_STR + row] = kv.w;
            float4 vv = *(const float4*)(Vb + (size_t)(k0 + row) * KD_ + d4);
            *(float4*)(Vs + row * HD + d4) = vv;
        }
        __syncthreads();

        float s[4][4];
#pragma unroll
        for (int i = 0; i < 4; i++)
#pragma unroll
            for (int j = 0; j < 4; j++) s[i][j] = 0.f;
#pragma unroll 16
        for (int d = 0; d < HD; d++) {
            float a[4], bb[4];
            *(float4*)a  = *(const float4*)(Qs + d * FA_STR + ty * 4);
            *(float4*)bb = *(const float4*)(Ks + d * FA_STR + tx * 4);
#pragma unroll
            for (int i = 0; i < 4; i++)
#pragma unroll
                for (int j = 0; j < 4; j++)
                    s[i][j] += a[i] * bb[j];
        }

        const bool diag = (kt == qt);
#pragma unroll
        for (int i = 0; i < 4; i++)
#pragma unroll
            for (int j = 0; j < 4; j++) {
                float val = s[i][j] * scale;
                if (diag && (tx * 4 + j) > (ty * 4 + i)) val = -1e30f;
                s[i][j] = val;
            }

#pragma unroll
        for (int i = 0; i < 4; i++) {
            float m = fmaxf(fmaxf(s[i][0], s[i][1]), fmaxf(s[i][2], s[i][3]));
            redm[(ty * 4 + i) * 17 + tx] = m;
        }
        __syncthreads();

        float mnew[4], fac[4];
#pragma unroll
        for (int i = 0; i < 4; i++) {
            float m = mrow[i];
#pragma unroll
            for (int t = 0; t < 16; t++)
                m = fmaxf(m, redm[(ty * 4 + i) * 17 + t]);
            mnew[i] = m;
            fac[i]  = __expf(mrow[i] - m);
            mrow[i] = m;
        }

#pragma unroll
        for (int i = 0; i < 4; i++) {
            float psum = 0.f;
#pragma unroll
            for (int j = 0; j < 4; j++) {
                float p = __expf(s[i][j] - mnew[i]);
                psum += p;
                Ps[(tx * 4 + j) * FA_STR + ty * 4 + i] = p;
            }
            reds[(ty * 4 + i) * 17 + tx] = psum;
            lrow[i] *= fac[i];
#pragma unroll
            for (int j = 0; j < 4; j++) o[i][j] *= fac[i];
        }
        __syncthreads();

#pragma unroll
        for (int i = 0; i < 4; i++) {
            float sum = 0.f;
#pragma unroll
            for (int t = 0; t < 16; t++)
                sum += reds[(ty * 4 + i) * 17 + t];
            lrow[i] += sum;
        }

#pragma unroll 16
        for (int j = 0; j < BK; j++) {
            float pa[4], va[4];
            *(float4*)pa = *(const float4*)(Ps + j * FA_STR + ty * 4);
            *(float4*)va = *(const float4*)(Vs + j * HD + tx * 4);
#pragma unroll
            for (int i = 0; i < 4; i++)
#pragma unroll
                for (int jj = 0; jj < 4; jj++)
                    o[i][jj] += pa[i] * va[jj];
        }
        __syncthreads();
    }

    float* Ob = O + (size_t)b * KS_ * KD_ + (size_t)h * KHD_;
#pragma unroll
    for (int i = 0; i < 4; i++) {
        int row = q0 + ty * 4 + i;
        float inv = 1.f / lrow[i];
        float4 out;
        out.x = o[i][0] * inv;
        out.y = o[i][1] * inv;
        out.z = o[i][2] * inv;
        out.w = o[i][3] * inv;
        *(float4*)(Ob + (size_t)row * KD_ + tx * 4) = out;
    }
}

// ---------------------------------------------------------------------------
// Launch
// ---------------------------------------------------------------------------
extern "C" void kernel_launch(void* const* d_in, const int* in_sizes, int n_in,
                              void* d_out, int out_size)
{
    (void)in_sizes; (void)n_in; (void)out_size;
    const float* x  = (const float*)d_in[0];
    const float* Wq = (const float*)d_in[1];
    const float* bq = (const float*)d_in[2];
    const float* Wk = (const float*)d_in[3];
    const float* bk = (const float*)d_in[4];
    const float* Wv = (const float*)d_in[5];
    const float* bv = (const float*)d_in[6];
    const float* Wo = (const float*)d_in[7];
    const float* bo = (const float*)d_in[8];
    float* out = (float*)d_out;

    float *q, *k, *v, *att;
    cudaGetSymbolAddress((void**)&q,   g_q);
    cudaGetSymbolAddress((void**)&k,   g_k);
    cudaGetSymbolAddress((void**)&v,   g_v);
    cudaGetSymbolAddress((void**)&att, g_att);

    const int gemm_smem = GST * (ASLOT + BSLOT) * (int)sizeof(float);  // 107520
    cudaFuncSetAttribute(gemm_tf32, cudaFuncAttributeMaxDynamicSharedMemorySize, gemm_smem);

    const int fa_smem = (64 * FA_STR * 3 + 64 * 64 + 2 * 64 * 17) * (int)sizeof(float);
    cudaFuncSetAttribute(flash_attn, cudaFuncAttributeMaxDynamicSharedMemorySize, fa_smem);

    dim3 gGrid(KD_ / GBN, KM_ / GBM);   // (8, 32)
    gemm_tf32<<<gGrid, 256, gemm_smem>>>(x, Wq, bq, q);
    gemm_tf32<<<gGrid, 256, gemm_smem>>>(x, Wk, bk, k);
    gemm_tf32<<<gGrid, 256, gemm_smem>>>(x, Wv, bv, v);

    dim3 faGrid(KS_ / 64, KH_, KB_);
    flash_attn<<<faGrid, 256, fa_smem>>>(q, k, v, att);

    gemm_tf32<<<gGrid, 256, gemm_smem>>>(att, Wo, bo, out);
}

// round 5
// speedup vs baseline: 3.0350x; 2.0186x over previous
#include <cuda_runtime.h>
#include <cstdint>

// Problem constants
#define KB_  2
#define KS_  2048
#define KD_  1024
#define KH_  16
#define KHD_ 64
#define KM_  (KB_ * KS_)   // 4096 rows

// Scratch (allocation-free rule: __device__ globals)
__device__ float g_q[(size_t)KM_ * KD_];
__device__ float g_k[(size_t)KM_ * KD_];
__device__ float g_v[(size_t)KM_ * KD_];
__device__ float g_att[(size_t)KM_ * KD_];

// ===========================================================================
// Helpers
// ===========================================================================
__device__ __forceinline__ void cpa16(uint32_t dst, const float* src) {
    asm volatile("cp.async.cg.shared.global [%0], [%1], 16;"
                 :: "r"(dst), "l"(src));
}
template <int N>
__device__ __forceinline__ void cpwait() {
    asm volatile("cp.async.wait_group %0;" :: "n"(N) : "memory");
}
__device__ __forceinline__ uint32_t s2u(const void* p) {
    uint32_t a;
    asm("{ .reg .u64 t; cvta.to.shared.u64 t, %1; cvt.u32.u64 %0, t; }"
        : "=r"(a) : "l"(p));
    return a;
}
__device__ __forceinline__ uint32_t f2tf32(float f) {
    uint32_t u;
    asm("cvt.rna.tf32.f32 %0, %1;" : "=r"(u) : "f"(f));
    return u;
}
// D += A(16x8) * B(8x8), tf32 inputs, fp32 accumulate
__device__ __forceinline__ void mma_tf32(float* c, const uint32_t* a, const uint32_t* b) {
    asm volatile(
        "mma.sync.aligned.m16n8k8.row.col.f32.tf32.tf32.f32 "
        "{%0,%1,%2,%3}, {%4,%5,%6,%7}, {%8,%9}, {%0,%1,%2,%3};"
        : "+f"(c[0]), "+f"(c[1]), "+f"(c[2]), "+f"(c[3])
        : "r"(a[0]), "r"(a[1]), "r"(a[2]), "r"(a[3]), "r"(b[0]), "r"(b[1]));
}

// ===========================================================================
// tf32 mma.sync GEMM (unchanged from round 4)
// ===========================================================================
#define GBM 128
#define GBN 128
#define GBK 32
#define GST 3
#define GNC (KD_ / GBK)
#define ASTR 36
#define BSTR 136
#define ASLOT (GBM * ASTR)
#define BSLOT (GBK * BSTR)

__device__ __forceinline__ void g_load_chunk(
    const float* __restrict__ Ag, const float* __restrict__ Wg,
    uint32_t as, uint32_t bs, int tid)
{
#pragma unroll
    for (int i = 0; i < 4; i++) {
        int idx = tid + i * 256;
        int r = idx >> 3, c4 = (idx & 7) * 4;
        cpa16(as + (uint32_t)(r * ASTR + c4) * 4, Ag + (size_t)r * KD_ + c4);
    }
#pragma unroll
    for (int i = 0; i < 4; i++) {
        int idx = tid + i * 256;
        int r = idx >> 5, c4 = (idx & 31) * 4;
        cpa16(bs + (uint32_t)(r * BSTR + c4) * 4, Wg + (size_t)r * KD_ + c4);
    }
    asm volatile("cp.async.commit_group;" ::: "memory");
}

__global__ __launch_bounds__(256, 2) void gemm_tf32(
    const float* __restrict__ A, const float* __restrict__ W,
    const float* __restrict__ bias, float* __restrict__ C)
{
    extern __shared__ float smem[];
    float* As = smem;
    float* Bs = smem + GST * ASLOT;
    const uint32_t as_u = s2u(As);
    const uint32_t bs_u = s2u(Bs);

    const int tid  = threadIdx.x;
    const int wid  = tid >> 5, lane = tid & 31;
    const int wm   = wid >> 2;
    const int wn   = wid & 3;
    const int gid  = lane >> 2;
    const int tig  = lane & 3;
    const int bm   = blockIdx.y * GBM;
    const int bn   = blockIdx.x * GBN;

    const float* Abase = A + (size_t)bm * KD_;
    const float* Wbase = W + bn;

    float acc[4][4][4];
#pragma unroll
    for (int mt = 0; mt < 4; mt++)
#pragma unroll
        for (int nt = 0; nt < 4; nt++)
#pragma unroll
            for (int r = 0; r < 4; r++) acc[mt][nt][r] = 0.f;

    g_load_chunk(Abase, Wbase, as_u, bs_u, tid);
    g_load_chunk(Abase + GBK, Wbase + (size_t)GBK * KD_,
                 as_u + ASLOT * 4, bs_u + BSLOT * 4, tid);

    for (int kc = 0; kc < GNC; kc++) {
        if (kc == GNC - 1) cpwait<0>(); else cpwait<1>();
        __syncthreads();

        const int kn = kc + 2;
        if (kn < GNC) {
            const int sl = kn % GST;
            g_load_chunk(Abase + kn * GBK, Wbase + (size_t)(kn * GBK) * KD_,
                         as_u + (uint32_t)sl * ASLOT * 4,
                         bs_u + (uint32_t)sl * BSLOT * 4, tid);
        }

        const float* Ac = As + (kc % GST) * ASLOT;
        const float* Bc = Bs + (kc % GST) * BSLOT;
#pragma unroll
        for (int ks = 0; ks < 4; ks++) {
            const int k0 = ks * 8;
            uint32_t af[4][4], bf[4][2];
#pragma unroll
            for (int mt = 0; mt < 4; mt++) {
                const int r0 = wm * 64 + mt * 16 + gid;
                af[mt][0] = f2tf32(Ac[r0 * ASTR + k0 + tig]);
                af[mt][1] = f2tf32(Ac[(r0 + 8) * ASTR + k0 + tig]);
                af[mt][2] = f2tf32(Ac[r0 * ASTR + k0 + tig + 4]);
                af[mt][3] = f2tf32(Ac[(r0 + 8) * ASTR + k0 + tig + 4]);
            }
#pragma unroll
            for (int nt = 0; nt < 4; nt++) {
                const int n0 = wn * 32 + nt * 8 + gid;
                bf[nt][0] = f2tf32(Bc[(k0 + tig) * BSTR + n0]);
                bf[nt][1] = f2tf32(Bc[(k0 + tig + 4) * BSTR + n0]);
            }
#pragma unroll
            for (int mt = 0; mt < 4; mt++)
#pragma unroll
                for (int nt = 0; nt < 4; nt++)
                    mma_tf32(acc[mt][nt], af[mt], bf[nt]);
        }
        __syncthreads();
    }

#pragma unroll
    for (int mt = 0; mt < 4; mt++) {
        const int r0 = bm + wm * 64 + mt * 16 + gid;
#pragma unroll
        for (int nt = 0; nt < 4; nt++) {
            const int col = bn + wn * 32 + nt * 8 + 2 * tig;
            const float b0 = bias[col], b1 = bias[col + 1];
            float2 v0 = make_float2(acc[mt][nt][0] + b0, acc[mt][nt][1] + b1);
            float2 v1 = make_float2(acc[mt][nt][2] + b0, acc[mt][nt][3] + b1);
            *(float2*)(C + (size_t)r0 * KD_ + col)       = v0;
            *(float2*)(C + (size_t)(r0 + 8) * KD_ + col) = v1;
        }
    }
}

// ===========================================================================
// Flash attention, tf32 mma.sync. BQ=128 per CTA, KV tiles of 64.
// 8 warps, warp w owns rows [w*16, w*16+16). Softmax in registers
// (shfl over the 4-lane tig group). P round-trips smem for frag relayout
// (warp-private rows -> no sync needed).
// Strides: Qs/Ks/Ps 68 (frag bank = 4*gid+tig, CF), Vs 72 (8*tig+gid, CF).
// ===========================================================================
#define FBQ   128
#define FBK   64
#define FQSTR 68
#define FKSTR 68
#define FVSTR 72
#define FPSTR 68

__global__ __launch_bounds__(256, 2) void flash_attn_mma(
    const float* __restrict__ Q, const float* __restrict__ K,
    const float* __restrict__ V, float* __restrict__ O)
{
    extern __shared__ float sm[];
    float* Qs = sm;                      // [128][68]
    float* Ps = Qs + FBQ * FQSTR;        // [128][68]
    float* Ks = Ps + FBQ * FPSTR;        // [64][68]
    float* Vs = Ks + FBK * FKSTR;        // [64][72]

    const int tid  = threadIdx.x;
    const int wid  = tid >> 5, lane = tid & 31;
    const int gid  = lane >> 2;          // 0..7
    const int tig  = lane & 3;           // 0..3
    const int qt   = (KS_ / FBQ - 1) - blockIdx.x;   // heavy tiles first
    const int h    = blockIdx.y;
    const int b    = blockIdx.z;
    const int q0   = qt * FBQ;
    const int r0   = wid * 16 + gid;     // warp-local row (lane's row 0)

    const float* Qb = Q + (size_t)b * KS_ * KD_ + (size_t)h * KHD_;
    const float* Kb = K + (size_t)b * KS_ * KD_ + (size_t)h * KHD_;
    const float* Vb = V + (size_t)b * KS_ * KD_ + (size_t)h * KHD_;

    // Load Q tile, fold scale 1/8, pre-round to tf32
#pragma unroll
    for (int i = 0; i < 8; i++) {
        int idx = tid + i * 256;
        int row = idx >> 4;
        int c4  = (idx & 15) * 4;
        float4 v4 = *(const float4*)(Qb + (size_t)(q0 + row) * KD_ + c4);
        uint4 u;
        u.x = f2tf32(v4.x * 0.125f);
        u.y = f2tf32(v4.y * 0.125f);
        u.z = f2tf32(v4.z * 0.125f);
        u.w = f2tf32(v4.w * 0.125f);
        *(uint4*)(Qs + row * FQSTR + c4) = *(uint4*)&u;
    }

    float oacc[8][4];
#pragma unroll
    for (int f = 0; f < 8; f++)
#pragma unroll
        for (int r = 0; r < 4; r++) oacc[f][r] = 0.f;
    float mstate[2] = {-1e30f, -1e30f};
    float lstate[2] = {0.f, 0.f};

    const int ntiles = 2 * qt + 2;
    for (int kt = 0; kt < ntiles; kt++) {
        const int k0g = kt * FBK;
        __syncthreads();   // previous tile's MMAs done before overwriting Ks/Vs
        // Load K,V tile (64x64), pre-round to tf32
#pragma unroll
        for (int i = 0; i < 4; i++) {
            int idx = tid + i * 256;
            int row = idx >> 4;
            int c4  = (idx & 15) * 4;
            float4 kv = *(const float4*)(Kb + (size_t)(k0g + row) * KD_ + c4);
            uint4 uk;
            uk.x = f2tf32(kv.x); uk.y = f2tf32(kv.y);
            uk.z = f2tf32(kv.z); uk.w = f2tf32(kv.w);
            *(uint4*)(Ks + row * FKSTR + c4) = uk;
            float4 vv = *(const float4*)(Vb + (size_t)(k0g + row) * KD_ + c4);
            uint4 uv;
            uv.x = f2tf32(vv.x); uv.y = f2tf32(vv.y);
            uv.z = f2tf32(vv.z); uv.w = f2tf32(vv.w);
            *(uint4*)(Vs + row * FVSTR + c4) = uv;
        }
        __syncthreads();

        // S = Q K^T : warp tile 16x64, 8 n-frags, 8 k-steps
        float sacc[8][4];
#pragma unroll
        for (int f = 0; f < 8; f++)
#pragma unroll
            for (int r = 0; r < 4; r++) sacc[f][r] = 0.f;
#pragma unroll
        for (int k8 = 0; k8 < 8; k8++) {
            uint32_t a[4];
            a[0] = __float_as_uint(Qs[r0 * FQSTR + k8 * 8 + tig]);
            a[1] = __float_as_uint(Qs[(r0 + 8) * FQSTR + k8 * 8 + tig]);
            a[2] = __float_as_uint(Qs[r0 * FQSTR + k8 * 8 + tig + 4]);
            a[3] = __float_as_uint(Qs[(r0 + 8) * FQSTR + k8 * 8 + tig + 4]);
#pragma unroll
            for (int f = 0; f < 8; f++) {
                uint32_t bb[2];
                bb[0] = __float_as_uint(Ks[(f * 8 + gid) * FKSTR + k8 * 8 + tig]);
                bb[1] = __float_as_uint(Ks[(f * 8 + gid) * FKSTR + k8 * 8 + tig + 4]);
                mma_tf32(sacc[f], a, bb);
            }
        }

        // Causal mask: only the last two tiles can cross the diagonal
        if (kt >= 2 * qt) {
            const int qrow0 = q0 + wid * 16 + gid;
#pragma unroll
            for (int f = 0; f < 8; f++) {
                const int kc = k0g + f * 8 + 2 * tig;
                if (kc     > qrow0)     sacc[f][0] = -1e30f;
                if (kc + 1 > qrow0)     sacc[f][1] = -1e30f;
                if (kc     > qrow0 + 8) sacc[f][2] = -1e30f;
                if (kc + 1 > qrow0 + 8) sacc[f][3] = -1e30f;
            }
        }

        // Row max (2 rows per thread), reduce over tig group
        float mx0 = -1e30f, mx1 = -1e30f;
#pragma unroll
        for (int f = 0; f < 8; f++) {
            mx0 = fmaxf(mx0, fmaxf(sacc[f][0], sacc[f][1]));
            mx1 = fmaxf(mx1, fmaxf(sacc[f][2], sacc[f][3]));
        }
        mx0 = fmaxf(mx0, __shfl_xor_sync(0xFFFFFFFF, mx0, 1));
        mx0 = fmaxf(mx0, __shfl_xor_sync(0xFFFFFFFF, mx0, 2));
        mx1 = fmaxf(mx1, __shfl_xor_sync(0xFFFFFFFF, mx1, 1));
        mx1 = fmaxf(mx1, __shfl_xor_sync(0xFFFFFFFF, mx1, 2));

        const float mnew0 = fmaxf(mstate[0], mx0);
        const float mnew1 = fmaxf(mstate[1], mx1);
        const float fac0 = __expf(mstate[0] - mnew0);
        const float fac1 = __expf(mstate[1] - mnew1);
        mstate[0] = mnew0; mstate[1] = mnew1;

        // P = exp(S - m), row sums, store tf32 P to warp-private smem rows
        float ls0 = 0.f, ls1 = 0.f;
#pragma unroll
        for (int f = 0; f < 8; f++) {
            float p0 = __expf(sacc[f][0] - mnew0);
            float p1 = __expf(sacc[f][1] - mnew0);
            float p2 = __expf(sacc[f][2] - mnew1);
            float p3 = __expf(sacc[f][3] - mnew1);
            ls0 += p0 + p1;
            ls1 += p2 + p3;
            uint2 w0 = make_uint2(f2tf32(p0), f2tf32(p1));
            uint2 w1 = make_uint2(f2tf32(p2), f2tf32(p3));
            *(uint2*)(Ps + r0 * FPSTR + f * 8 + 2 * tig)       = w0;
            *(uint2*)(Ps + (r0 + 8) * FPSTR + f * 8 + 2 * tig) = w1;
        }
        ls0 += __shfl_xor_sync(0xFFFFFFFF, ls0, 1);
        ls0 += __shfl_xor_sync(0xFFFFFFFF, ls0, 2);
        ls1 += __shfl_xor_sync(0xFFFFFFFF, ls1, 1);
        ls1 += __shfl_xor_sync(0xFFFFFFFF, ls1, 2);
        lstate[0] = lstate[0] * fac0 + ls0;
        lstate[1] = lstate[1] * fac1 + ls1;

        // Rescale O
#pragma unroll
        for (int f = 0; f < 8; f++) {
            oacc[f][0] *= fac0; oacc[f][1] *= fac0;
            oacc[f][2] *= fac1; oacc[f][3] *= fac1;
        }
        __syncwarp();   // Ps rows visible within the warp

        // O += P V : 8 d-frags, 8 k-steps over the 64 keys
#pragma unroll
        for (int k8 = 0; k8 < 8; k8++) {
            uint32_t a[4];
            a[0] = __float_as_uint(Ps[r0 * FPSTR + k8 * 8 + tig]);
            a[1] = __float_as_uint(Ps[(r0 + 8) * FPSTR + k8 * 8 + tig]);
            a[2] = __float_as_uint(Ps[r0 * FPSTR + k8 * 8 + tig + 4]);
            a[3] = __float_as_uint(Ps[(r0 + 8) * FPSTR + k8 * 8 + tig + 4]);
#pragma unroll
            for (int f = 0; f < 8; f++) {
                uint32_t bb[2];
                bb[0] = __float_as_uint(Vs[(k8 * 8 + tig) * FVSTR + f * 8 + gid]);
                bb[1] = __float_as_uint(Vs[(k8 * 8 + tig + 4) * FVSTR + f * 8 + gid]);
                mma_tf32(oacc[f], a, bb);
            }
        }
    }

    // Normalize + write out, (B,S,D) layout
    const float inv0 = 1.f / lstate[0];
    const float inv1 = 1.f / lstate[1];
    float* Ob = O + (size_t)b * KS_ * KD_ + (size_t)h * KHD_;
    const int qrow0 = q0 + wid * 16 + gid;
#pragma unroll
    for (int f = 0; f < 8; f++) {
        const int col = f * 8 + 2 * tig;
        float2 v0 = make_float2(oacc[f][0] * inv0, oacc[f][1] * inv0);
        float2 v1 = make_float2(oacc[f][2] * inv1, oacc[f][3] * inv1);
        *(float2*)(Ob + (size_t)qrow0 * KD_ + col)       = v0;
        *(float2*)(Ob + (size_t)(qrow0 + 8) * KD_ + col) = v1;
    }
}

// ---------------------------------------------------------------------------
// Launch
// ---------------------------------------------------------------------------
extern "C" void kernel_launch(void* const* d_in, const int* in_sizes, int n_in,
                              void* d_out, int out_size)
{
    (void)in_sizes; (void)n_in; (void)out_size;
    const float* x  = (const float*)d_in[0];
    const float* Wq = (const float*)d_in[1];
    const float* bq = (const float*)d_in[2];
    const float* Wk = (const float*)d_in[3];
    const float* bk = (const float*)d_in[4];
    const float* Wv = (const float*)d_in[5];
    const float* bv = (const float*)d_in[6];
    const float* Wo = (const float*)d_in[7];
    const float* bo = (const float*)d_in[8];
    float* out = (float*)d_out;

    float *q, *k, *v, *att;
    cudaGetSymbolAddress((void**)&q,   g_q);
    cudaGetSymbolAddress((void**)&k,   g_k);
    cudaGetSymbolAddress((void**)&v,   g_v);
    cudaGetSymbolAddress((void**)&att, g_att);

    const int gemm_smem = GST * (ASLOT + BSLOT) * (int)sizeof(float);
    cudaFuncSetAttribute(gemm_tf32, cudaFuncAttributeMaxDynamicSharedMemorySize, gemm_smem);

    const int fa_smem = (FBQ * FQSTR + FBQ * FPSTR + FBK * FKSTR + FBK * FVSTR)
                        * (int)sizeof(float);   // 105,472 B
    cudaFuncSetAttribute(flash_attn_mma, cudaFuncAttributeMaxDynamicSharedMemorySize, fa_smem);

    dim3 gGrid(KD_ / GBN, KM_ / GBM);
    gemm_tf32<<<gGrid, 256, gemm_smem>>>(x, Wq, bq, q);
    gemm_tf32<<<gGrid, 256, gemm_smem>>>(x, Wk, bk, k);
    gemm_tf32<<<gGrid, 256, gemm_smem>>>(x, Wv, bv, v);

    dim3 faGrid(KS_ / FBQ, KH_, KB_);   // (16, 16, 2)
    flash_attn_mma<<<faGrid, 256, fa_smem>>>(q, k, v, att);

    gemm_tf32<<<gGrid, 256, gemm_smem>>>(att, Wo, bo, out);
}

// round 6
// speedup vs baseline: 3.1943x; 1.0525x over previous
#include <cuda_runtime.h>
#include <cstdint>

// Problem constants
#define KB_  2
#define KS_  2048
#define KD_  1024
#define KH_  16
#define KHD_ 64
#define KM_  (KB_ * KS_)   // 4096 rows

// Scratch (allocation-free rule: __device__ globals)
__device__ float g_q[(size_t)KM_ * KD_];
__device__ float g_k[(size_t)KM_ * KD_];
__device__ float g_v[(size_t)KM_ * KD_];
__device__ float g_att[(size_t)KM_ * KD_];

// ===========================================================================
// Helpers
// ===========================================================================
__device__ __forceinline__ void cpa16(uint32_t dst, const float* src) {
    asm volatile("cp.async.cg.shared.global [%0], [%1], 16;"
                 :: "r"(dst), "l"(src));
}
template <int N>
__device__ __forceinline__ void cpwait() {
    asm volatile("cp.async.wait_group %0;" :: "n"(N) : "memory");
}
__device__ __forceinline__ uint32_t s2u(const void* p) {
    uint32_t a;
    asm("{ .reg .u64 t; cvta.to.shared.u64 t, %1; cvt.u32.u64 %0, t; }"
        : "=r"(a) : "l"(p));
    return a;
}
__device__ __forceinline__ uint32_t f2tf32(float f) {
    uint32_t u;
    asm("cvt.rna.tf32.f32 %0, %1;" : "=r"(u) : "f"(f));
    return u;
}
__device__ __forceinline__ float ex2(float x) {
    float y;
    asm("ex2.approx.f32 %0, %1;" : "=f"(y) : "f"(x));
    return y;
}
// D += A(16x8) * B(8x8), tf32 inputs, fp32 accumulate
__device__ __forceinline__ void mma_tf32(float* c, const uint32_t* a, const uint32_t* b) {
    asm volatile(
        "mma.sync.aligned.m16n8k8.row.col.f32.tf32.tf32.f32 "
        "{%0,%1,%2,%3}, {%4,%5,%6,%7}, {%8,%9}, {%0,%1,%2,%3};"
        : "+f"(c[0]), "+f"(c[1]), "+f"(c[2]), "+f"(c[3])
        : "r"(a[0]), "r"(a[1]), "r"(a[2]), "r"(a[3]), "r"(b[0]), "r"(b[1]));
}

// ===========================================================================
// tf32 mma.sync GEMM core (CTA tile 128x128x32, 3-stage cp.async)
// ===========================================================================
#define GBM 128
#define GBN 128
#define GBK 32
#define GST 3
#define GNC (KD_ / GBK)
#define ASTR 36
#define BSTR 136
#define ASLOT (GBM * ASTR)
#define BSLOT (GBK * BSTR)

__device__ __forceinline__ void g_load_chunk(
    const float* __restrict__ Ag, const float* __restrict__ Wg,
    uint32_t as, uint32_t bs, int tid)
{
#pragma unroll
    for (int i = 0; i < 4; i++) {
        int idx = tid + i * 256;
        int r = idx >> 3, c4 = (idx & 7) * 4;
        cpa16(as + (uint32_t)(r * ASTR + c4) * 4, Ag + (size_t)r * KD_ + c4);
    }
#pragma unroll
    for (int i = 0; i < 4; i++) {
        int idx = tid + i * 256;
        int r = idx >> 5, c4 = (idx & 31) * 4;
        cpa16(bs + (uint32_t)(r * BSTR + c4) * 4, Wg + (size_t)r * KD_ + c4);
    }
    asm volatile("cp.async.commit_group;" ::: "memory");
}

__device__ __forceinline__ void gemm_body(
    const float* __restrict__ A, const float* __restrict__ W,
    const float* __restrict__ bias, float* __restrict__ C,
    int bm, int bn)
{
    extern __shared__ float smem[];
    float* As = smem;
    float* Bs = smem + GST * ASLOT;
    const uint32_t as_u = s2u(As);
    const uint32_t bs_u = s2u(Bs);

    const int tid  = threadIdx.x;
    const int wid  = tid >> 5, lane = tid & 31;
    const int wm   = wid >> 2;
    const int wn   = wid & 3;
    const int gid  = lane >> 2;
    const int tig  = lane & 3;

    const float* Abase = A + (size_t)bm * KD_;
    const float* Wbase = W + bn;

    float acc[4][4][4];
#pragma unroll
    for (int mt = 0; mt < 4; mt++)
#pragma unroll
        for (int nt = 0; nt < 4; nt++)
#pragma unroll
            for (int r = 0; r < 4; r++) acc[mt][nt][r] = 0.f;

    g_load_chunk(Abase, Wbase, as_u, bs_u, tid);
    g_load_chunk(Abase + GBK, Wbase + (size_t)GBK * KD_,
                 as_u + ASLOT * 4, bs_u + BSLOT * 4, tid);

    for (int kc = 0; kc < GNC; kc++) {
        if (kc == GNC - 1) cpwait<0>(); else cpwait<1>();
        __syncthreads();

        const int kn = kc + 2;
        if (kn < GNC) {
            const int sl = kn % GST;
            g_load_chunk(Abase + kn * GBK, Wbase + (size_t)(kn * GBK) * KD_,
                         as_u + (uint32_t)sl * ASLOT * 4,
                         bs_u + (uint32_t)sl * BSLOT * 4, tid);
        }

        const float* Ac = As + (kc % GST) * ASLOT;
        const float* Bc = Bs + (kc % GST) * BSLOT;
#pragma unroll
        for (int ks = 0; ks < 4; ks++) {
            const int k0 = ks * 8;
            uint32_t af[4][4], bf[4][2];
#pragma unroll
            for (int mt = 0; mt < 4; mt++) {
                const int r0 = wm * 64 + mt * 16 + gid;
                af[mt][0] = f2tf32(Ac[r0 * ASTR + k0 + tig]);
                af[mt][1] = f2tf32(Ac[(r0 + 8) * ASTR + k0 + tig]);
                af[mt][2] = f2tf32(Ac[r0 * ASTR + k0 + tig + 4]);
                af[mt][3] = f2tf32(Ac[(r0 + 8) * ASTR + k0 + tig + 4]);
            }
#pragma unroll
            for (int nt = 0; nt < 4; nt++) {
                const int n0 = wn * 32 + nt * 8 + gid;
                bf[nt][0] = f2tf32(Bc[(k0 + tig) * BSTR + n0]);
                bf[nt][1] = f2tf32(Bc[(k0 + tig + 4) * BSTR + n0]);
            }
#pragma unroll
            for (int mt = 0; mt < 4; mt++)
#pragma unroll
                for (int nt = 0; nt < 4; nt++)
                    mma_tf32(acc[mt][nt], af[mt], bf[nt]);
        }
        __syncthreads();
    }

#pragma unroll
    for (int mt = 0; mt < 4; mt++) {
        const int r0 = bm + wm * 64 + mt * 16 + gid;
#pragma unroll
        for (int nt = 0; nt < 4; nt++) {
            const int col = bn + wn * 32 + nt * 8 + 2 * tig;
            const float b0 = bias[col], b1 = bias[col + 1];
            float2 v0 = make_float2(acc[mt][nt][0] + b0, acc[mt][nt][1] + b1);
            float2 v1 = make_float2(acc[mt][nt][2] + b0, acc[mt][nt][3] + b1);
            *(float2*)(C + (size_t)r0 * KD_ + col)       = v0;
            *(float2*)(C + (size_t)(r0 + 8) * KD_ + col) = v1;
        }
    }
}

// Fused Q/K/V projection: blockIdx.z selects weight/bias/output
__global__ __launch_bounds__(256, 2) void gemm_qkv(
    const float* __restrict__ x,
    const float* __restrict__ Wq, const float* __restrict__ bq, float* __restrict__ q,
    const float* __restrict__ Wk, const float* __restrict__ bk, float* __restrict__ k,
    const float* __restrict__ Wv, const float* __restrict__ bv, float* __restrict__ v)
{
    const float* W; const float* bias; float* C;
    if (blockIdx.z == 0)      { W = Wq; bias = bq; C = q; }
    else if (blockIdx.z == 1) { W = Wk; bias = bk; C = k; }
    else                      { W = Wv; bias = bv; C = v; }
    gemm_body(x, W, bias, C, blockIdx.y * GBM, blockIdx.x * GBN);
}

__global__ __launch_bounds__(256, 2) void gemm_tf32(
    const float* __restrict__ A, const float* __restrict__ W,
    const float* __restrict__ bias, float* __restrict__ C)
{
    gemm_body(A, W, bias, C, blockIdx.y * GBM, blockIdx.x * GBN);
}

// ===========================================================================
// Flash attention, tf32 mma.sync. BQ=128, KV tiles of 64.
// Q fragments hoisted to registers (Q staging region reused as Ps).
// Next tile's K/V prefetched raw via cp.async, converted smem->smem.
// ===========================================================================
#define FBQ   128
#define FBK   64
#define FKSTR 68
#define FVSTR 72
#define FPSTR 68
// smem float offsets
#define OFF_PS   0                         // [128][68]  (also Q staging)
#define OFF_KS   (FBQ * FPSTR)             // [64][68]
#define OFF_VS   (OFF_KS + FBK * FKSTR)    // [64][72]
#define OFF_KRAW (OFF_VS + FBK * FVSTR)    // [64][64]
#define OFF_VRAW (OFF_KRAW + FBK * 64)     // [64][64]
#define FA_SMEMF (OFF_VRAW + FBK * 64)     // 25856 floats = 103424 B

__global__ __launch_bounds__(256, 2) void flash_attn_mma(
    const float* __restrict__ Q, const float* __restrict__ K,
    const float* __restrict__ V, float* __restrict__ O)
{
    extern __shared__ float sm[];
    float* Ps   = sm + OFF_PS;
    float* Ks   = sm + OFF_KS;
    float* Vs   = sm + OFF_VS;
    float* Kraw = sm + OFF_KRAW;
    float* Vraw = sm + OFF_VRAW;
    const uint32_t kraw_u = s2u(Kraw);
    const uint32_t vraw_u = s2u(Vraw);

    const int tid  = threadIdx.x;
    const int wid  = tid >> 5, lane = tid & 31;
    const int gid  = lane >> 2;
    const int tig  = lane & 3;
    const int qt   = (KS_ / FBQ - 1) - blockIdx.x;   // heavy tiles first
    const int h    = blockIdx.y;
    const int b    = blockIdx.z;
    const int q0   = qt * FBQ;
    const int r0   = wid * 16 + gid;

    const float* Qb = Q + (size_t)b * KS_ * KD_ + (size_t)h * KHD_;
    const float* Kb = K + (size_t)b * KS_ * KD_ + (size_t)h * KHD_;
    const float* Vb = V + (size_t)b * KS_ * KD_ + (size_t)h * KHD_;

    const int ntiles = 2 * qt + 2;

    // Prefetch tile 0 raw K/V (overlaps with Q staging below)
#pragma unroll
    for (int i = 0; i < 4; i++) {
        int idx = tid + i * 256;
        int row = idx >> 4;
        int c4  = (idx & 15) * 4;
        cpa16(kraw_u + (uint32_t)idx * 16, Kb + (size_t)row * KD_ + c4);
        cpa16(vraw_u + (uint32_t)idx * 16, Vb + (size_t)row * KD_ + c4);
    }
    asm volatile("cp.async.commit_group;" ::: "memory");

    // Stage Q (scale = 0.125 * log2(e) folded), tf32-rounded, into Ps region
    const float qscale = 0.125f * 1.4426950408889634f;
#pragma unroll
    for (int i = 0; i < 8; i++) {
        int idx = tid + i * 256;
        int row = idx >> 4;
        int c4  = (idx & 15) * 4;
        float4 v4 = *(const float4*)(Qb + (size_t)(q0 + row) * KD_ + c4);
        uint4 u;
        u.x = f2tf32(v4.x * qscale);
        u.y = f2tf32(v4.y * qscale);
        u.z = f2tf32(v4.z * qscale);
        u.w = f2tf32(v4.w * qscale);
        *(uint4*)(Ps + row * FPSTR + c4) = u;
    }
    __syncthreads();

    // Hoist Q fragments to registers (rows are warp-private)
    uint32_t qf[8][4];
#pragma unroll
    for (int k8 = 0; k8 < 8; k8++) {
        qf[k8][0] = __float_as_uint(Ps[r0 * FPSTR + k8 * 8 + tig]);
        qf[k8][1] = __float_as_uint(Ps[(r0 + 8) * FPSTR + k8 * 8 + tig]);
        qf[k8][2] = __float_as_uint(Ps[r0 * FPSTR + k8 * 8 + tig + 4]);
        qf[k8][3] = __float_as_uint(Ps[(r0 + 8) * FPSTR + k8 * 8 + tig + 4]);
    }

    // Convert tile 0 raw -> Ks/Vs
    cpwait<0>();
    __syncthreads();
#pragma unroll
    for (int i = 0; i < 4; i++) {
        int idx = tid + i * 256;
        int row = idx >> 4;
        int c4  = (idx & 15) * 4;
        float4 kr = *(const float4*)(Kraw + row * 64 + c4);
        uint4 uk;
        uk.x = f2tf32(kr.x); uk.y = f2tf32(kr.y);
        uk.z = f2tf32(kr.z); uk.w = f2tf32(kr.w);
        *(uint4*)(Ks + row * FKSTR + c4) = uk;
        float4 vr = *(const float4*)(Vraw + row * 64 + c4);
        uint4 uv;
        uv.x = f2tf32(vr.x); uv.y = f2tf32(vr.y);
        uv.z = f2tf32(vr.z); uv.w = f2tf32(vr.w);
        *(uint4*)(Vs + row * FVSTR + c4) = uv;
    }
    __syncthreads();

    float oacc[8][4];
#pragma unroll
    for (int f = 0; f < 8; f++)
#pragma unroll
        for (int r = 0; r < 4; r++) oacc[f][r] = 0.f;
    float mstate[2] = {-1e30f, -1e30f};
    float lstate[2] = {0.f, 0.f};

    for (int kt = 0; kt < ntiles; kt++) {
        // Issue raw prefetch for next tile (hidden behind this tile's compute)
        if (kt + 1 < ntiles) {
            const int kn0 = (kt + 1) * FBK;
#pragma unroll
            for (int i = 0; i < 4; i++) {
                int idx = tid + i * 256;
                int row = idx >> 4;
                int c4  = (idx & 15) * 4;
                cpa16(kraw_u + (uint32_t)idx * 16, Kb + (size_t)(kn0 + row) * KD_ + c4);
                cpa16(vraw_u + (uint32_t)idx * 16, Vb + (size_t)(kn0 + row) * KD_ + c4);
            }
            asm volatile("cp.async.commit_group;" ::: "memory");
        }

        // S = Q K^T
        float sacc[8][4];
#pragma unroll
        for (int f = 0; f < 8; f++)
#pragma unroll
            for (int r = 0; r < 4; r++) sacc[f][r] = 0.f;
#pragma unroll
        for (int k8 = 0; k8 < 8; k8++) {
#pragma unroll
            for (int f = 0; f < 8; f++) {
                uint32_t bb[2];
                bb[0] = __float_as_uint(Ks[(f * 8 + gid) * FKSTR + k8 * 8 + tig]);
                bb[1] = __float_as_uint(Ks[(f * 8 + gid) * FKSTR + k8 * 8 + tig + 4]);
                mma_tf32(sacc[f], qf[k8], bb);
            }
        }

        // Causal mask (last two tiles only)
        if (kt >= 2 * qt) {
            const int k0g = kt * FBK;
            const int qrow0 = q0 + wid * 16 + gid;
#pragma unroll
            for (int f = 0; f < 8; f++) {
                const int kc = k0g + f * 8 + 2 * tig;
                if (kc     > qrow0)     sacc[f][0] = -1e30f;
                if (kc + 1 > qrow0)     sacc[f][1] = -1e30f;
                if (kc     > qrow0 + 8) sacc[f][2] = -1e30f;
                if (kc + 1 > qrow0 + 8) sacc[f][3] = -1e30f;
            }
        }

        // Row max over tig group
        float mx0 = -1e30f, mx1 = -1e30f;
#pragma unroll
        for (int f = 0; f < 8; f++) {
            mx0 = fmaxf(mx0, fmaxf(sacc[f][0], sacc[f][1]));
            mx1 = fmaxf(mx1, fmaxf(sacc[f][2], sacc[f][3]));
        }
        mx0 = fmaxf(mx0, __shfl_xor_sync(0xFFFFFFFF, mx0, 1));
        mx0 = fmaxf(mx0, __shfl_xor_sync(0xFFFFFFFF, mx0, 2));
        mx1 = fmaxf(mx1, __shfl_xor_sync(0xFFFFFFFF, mx1, 1));
        mx1 = fmaxf(mx1, __shfl_xor_sync(0xFFFFFFFF, mx1, 2));

        const float mnew0 = fmaxf(mstate[0], mx0);
        const float mnew1 = fmaxf(mstate[1], mx1);
        const float fac0 = ex2(mstate[0] - mnew0);
        const float fac1 = ex2(mstate[1] - mnew1);
        mstate[0] = mnew0; mstate[1] = mnew1;

        // P = 2^(S - m), row sums, store tf32 P (warp-private rows)
        float ls0 = 0.f, ls1 = 0.f;
#pragma unroll
        for (int f = 0; f < 8; f++) {
            float p0 = ex2(sacc[f][0] - mnew0);
            float p1 = ex2(sacc[f][1] - mnew0);
            float p2 = ex2(sacc[f][2] - mnew1);
            float p3 = ex2(sacc[f][3] - mnew1);
            ls0 += p0 + p1;
            ls1 += p2 + p3;
            uint2 w0 = make_uint2(f2tf32(p0), f2tf32(p1));
            uint2 w1 = make_uint2(f2tf32(p2), f2tf32(p3));
            *(uint2*)(Ps + r0 * FPSTR + f * 8 + 2 * tig)       = w0;
            *(uint2*)(Ps + (r0 + 8) * FPSTR + f * 8 + 2 * tig) = w1;
        }
        ls0 += __shfl_xor_sync(0xFFFFFFFF, ls0, 1);
        ls0 += __shfl_xor_sync(0xFFFFFFFF, ls0, 2);
        ls1 += __shfl_xor_sync(0xFFFFFFFF, ls1, 1);
        ls1 += __shfl_xor_sync(0xFFFFFFFF, ls1, 2);
        lstate[0] = lstate[0] * fac0 + ls0;
        lstate[1] = lstate[1] * fac1 + ls1;

#pragma unroll
        for (int f = 0; f < 8; f++) {
            oacc[f][0] *= fac0; oacc[f][1] *= fac0;
            oacc[f][2] *= fac1; oacc[f][3] *= fac1;
        }
        __syncwarp();

        // O += P V
#pragma unroll
        for (int k8 = 0; k8 < 8; k8++) {
            uint32_t a[4];
            a[0] = __float_as_uint(Ps[r0 * FPSTR + k8 * 8 + tig]);
            a[1] = __float_as_uint(Ps[(r0 + 8) * FPSTR + k8 * 8 + tig]);
            a[2] = __float_as_uint(Ps[r0 * FPSTR + k8 * 8 + tig + 4]);
            a[3] = __float_as_uint(Ps[(r0 + 8) * FPSTR + k8 * 8 + tig + 4]);
#pragma unroll
            for (int f = 0; f < 8; f++) {
                uint32_t bb[2];
                bb[0] = __float_as_uint(Vs[(k8 * 8 + tig) * FVSTR + f * 8 + gid]);
                bb[1] = __float_as_uint(Vs[(k8 * 8 + tig + 4) * FVSTR + f * 8 + gid]);
                mma_tf32(oacc[f], a, bb);
            }
        }

        // Convert prefetched raw -> Ks/Vs for next tile
        if (kt + 1 < ntiles) {
            cpwait<0>();
            __syncthreads();   // all MMAs done reading Ks/Vs; raw data arrived
#pragma unroll
            for (int i = 0; i < 4; i++) {
                int idx = tid + i * 256;
                int row = idx >> 4;
                int c4  = (idx & 15) * 4;
                float4 kr = *(const float4*)(Kraw + row * 64 + c4);
                uint4 uk;
                uk.x = f2tf32(kr.x); uk.y = f2tf32(kr.y);
                uk.z = f2tf32(kr.z); uk.w = f2tf32(kr.w);
                *(uint4*)(Ks + row * FKSTR + c4) = uk;
                float4 vr = *(const float4*)(Vraw + row * 64 + c4);
                uint4 uv;
                uv.x = f2tf32(vr.x); uv.y = f2tf32(vr.y);
                uv.z = f2tf32(vr.z); uv.w = f2tf32(vr.w);
                *(uint4*)(Vs + row * FVSTR + c4) = uv;
            }
            __syncthreads();
        }
    }

    // Normalize + write out, (B,S,D) layout
    const float inv0 = 1.f / lstate[0];
    const float inv1 = 1.f / lstate[1];
    float* Ob = O + (size_t)b * KS_ * KD_ + (size_t)h * KHD_;
    const int qrow0 = q0 + wid * 16 + gid;
#pragma unroll
    for (int f = 0; f < 8; f++) {
        const int col = f * 8 + 2 * tig;
        float2 v0 = make_float2(oacc[f][0] * inv0, oacc[f][1] * inv0);
        float2 v1 = make_float2(oacc[f][2] * inv1, oacc[f][3] * inv1);
        *(float2*)(Ob + (size_t)qrow0 * KD_ + col)       = v0;
        *(float2*)(Ob + (size_t)(qrow0 + 8) * KD_ + col) = v1;
    }
}

// ---------------------------------------------------------------------------
// Launch
// ---------------------------------------------------------------------------
extern "C" void kernel_launch(void* const* d_in, const int* in_sizes, int n_in,
                              void* d_out, int out_size)
{
    (void)in_sizes; (void)n_in; (void)out_size;
    const float* x  = (const float*)d_in[0];
    const float* Wq = (const float*)d_in[1];
    const float* bq = (const float*)d_in[2];
    const float* Wk = (const float*)d_in[3];
    const float* bk = (const float*)d_in[4];
    const float* Wv = (const float*)d_in[5];
    const float* bv = (const float*)d_in[6];
    const float* Wo = (const float*)d_in[7];
    const float* bo = (const float*)d_in[8];
    float* out = (float*)d_out;

    float *q, *k, *v, *att;
    cudaGetSymbolAddress((void**)&q,   g_q);
    cudaGetSymbolAddress((void**)&k,   g_k);
    cudaGetSymbolAddress((void**)&v,   g_v);
    cudaGetSymbolAddress((void**)&att, g_att);

    const int gemm_smem = GST * (ASLOT + BSLOT) * (int)sizeof(float);
    cudaFuncSetAttribute(gemm_qkv,  cudaFuncAttributeMaxDynamicSharedMemorySize, gemm_smem);
    cudaFuncSetAttribute(gemm_tf32, cudaFuncAttributeMaxDynamicSharedMemorySize, gemm_smem);

    const int fa_smem = FA_SMEMF * (int)sizeof(float);   // 103,424 B
    cudaFuncSetAttribute(flash_attn_mma, cudaFuncAttributeMaxDynamicSharedMemorySize, fa_smem);

    dim3 gGridQKV(KD_ / GBN, KM_ / GBM, 3);  // (8, 32, 3)
    gemm_qkv<<<gGridQKV, 256, gemm_smem>>>(x, Wq, bq, q, Wk, bk, k, Wv, bv, v);

    dim3 faGrid(KS_ / FBQ, KH_, KB_);        // (16, 16, 2)
    flash_attn_mma<<<faGrid, 256, fa_smem>>>(q, k, v, att);

    dim3 gGrid(KD_ / GBN, KM_ / GBM);        // (8, 32)
    gemm_tf32<<<gGrid, 256, gemm_smem>>>(att, Wo, bo, out);
}

// round 7
// speedup vs baseline: 3.2404x; 1.0144x over previous
#include <cuda_runtime.h>
#include <cstdint>

// Problem constants
#define KB_  2
#define KS_  2048
#define KD_  1024
#define KH_  16
#define KHD_ 64
#define KM_  (KB_ * KS_)   // 4096 rows

// Scratch (allocation-free rule: __device__ globals)
__device__ float g_q[(size_t)KM_ * KD_];
__device__ float g_k[(size_t)KM_ * KD_];
__device__ float g_v[(size_t)KM_ * KD_];
__device__ float g_att[(size_t)KM_ * KD_];
__device__ float g_x[(size_t)KM_ * KD_];        // tf32-rounded x
__device__ float g_w[4][(size_t)KD_ * KD_];     // tf32-rounded weights

// ===========================================================================
// Helpers
// ===========================================================================
__device__ __forceinline__ void cpa16(uint32_t dst, const float* src) {
    asm volatile("cp.async.cg.shared.global [%0], [%1], 16;"
                 :: "r"(dst), "l"(src));
}
template <int N>
__device__ __forceinline__ void cpwait() {
    asm volatile("cp.async.wait_group %0;" :: "n"(N) : "memory");
}
__device__ __forceinline__ uint32_t s2u(const void* p) {
    uint32_t a;
    asm("{ .reg .u64 t; cvta.to.shared.u64 t, %1; cvt.u32.u64 %0, t; }"
        : "=r"(a) : "l"(p));
    return a;
}
__device__ __forceinline__ uint32_t f2tf32(float f) {
    uint32_t u;
    asm("cvt.rna.tf32.f32 %0, %1;" : "=r"(u) : "f"(f));
    return u;
}
__device__ __forceinline__ float ex2(float x) {
    float y;
    asm("ex2.approx.f32 %0, %1;" : "=f"(y) : "f"(x));
    return y;
}
// D += A(16x8) * B(8x8), tf32 inputs, fp32 accumulate
__device__ __forceinline__ void mma_tf32(float* c, const uint32_t* a, const uint32_t* b) {
    asm volatile(
        "mma.sync.aligned.m16n8k8.row.col.f32.tf32.tf32.f32 "
        "{%0,%1,%2,%3}, {%4,%5,%6,%7}, {%8,%9}, {%0,%1,%2,%3};"
        : "+f"(c[0]), "+f"(c[1]), "+f"(c[2]), "+f"(c[3])
        : "r"(a[0]), "r"(a[1]), "r"(a[2]), "r"(a[3]), "r"(b[0]), "r"(b[1]));
}

// ===========================================================================
// Pre-round x + 4 weights to tf32 (rna), once per launch.
// z=0: x (KM_*KD_), z=1..4: weights (KD_*KD_).
// ===========================================================================
__global__ __launch_bounds__(256) void round_tf32_all(
    const float* __restrict__ x,
    const float* __restrict__ Wq, const float* __restrict__ Wk,
    const float* __restrict__ Wv, const float* __restrict__ Wo)
{
    const int z = blockIdx.z;
    const float* src;
    float* dst;
    size_t n4;   // element count / 4
    if (z == 0) { src = x;  dst = g_x;    n4 = (size_t)KM_ * KD_ / 4; }
    else {
        src = (z == 1) ? Wq : (z == 2) ? Wk : (z == 3) ? Wv : Wo;
        dst = g_w[z - 1];
        n4  = (size_t)KD_ * KD_ / 4;
    }
    const size_t stride = (size_t)gridDim.x * 256;
    for (size_t i = blockIdx.x * 256 + threadIdx.x; i < n4; i += stride) {
        float4 v = *(const float4*)(src + i * 4);
        uint4 u;
        u.x = f2tf32(v.x); u.y = f2tf32(v.y);
        u.z = f2tf32(v.z); u.w = f2tf32(v.w);
        *(uint4*)(dst + i * 4) = u;
    }
}

// ===========================================================================
// tf32 mma.sync GEMM core — inputs pre-rounded, NO cvt in inner loop.
// CTA tile 128x128x32, 3-stage cp.async.
// ===========================================================================
#define GBM 128
#define GBN 128
#define GBK 32
#define GST 3
#define GNC (KD_ / GBK)
#define ASTR 36
#define BSTR 136
#define ASLOT (GBM * ASTR)
#define BSLOT (GBK * BSTR)

__device__ __forceinline__ void g_load_chunk(
    const float* __restrict__ Ag, const float* __restrict__ Wg,
    uint32_t as, uint32_t bs, int tid)
{
#pragma unroll
    for (int i = 0; i < 4; i++) {
        int idx = tid + i * 256;
        int r = idx >> 3, c4 = (idx & 7) * 4;
        cpa16(as + (uint32_t)(r * ASTR + c4) * 4, Ag + (size_t)r * KD_ + c4);
    }
#pragma unroll
    for (int i = 0; i < 4; i++) {
        int idx = tid + i * 256;
        int r = idx >> 5, c4 = (idx & 31) * 4;
        cpa16(bs + (uint32_t)(r * BSTR + c4) * 4, Wg + (size_t)r * KD_ + c4);
    }
    asm volatile("cp.async.commit_group;" ::: "memory");
}

__device__ __forceinline__ void gemm_body(
    const float* __restrict__ A, const float* __restrict__ W,
    const float* __restrict__ bias, float* __restrict__ C,
    int bm, int bn)
{
    extern __shared__ float smem[];
    float* As = smem;
    float* Bs = smem + GST * ASLOT;
    const uint32_t as_u = s2u(As);
    const uint32_t bs_u = s2u(Bs);

    const int tid  = threadIdx.x;
    const int wid  = tid >> 5, lane = tid & 31;
    const int wm   = wid >> 2;
    const int wn   = wid & 3;
    const int gid  = lane >> 2;
    const int tig  = lane & 3;

    const float* Abase = A + (size_t)bm * KD_;
    const float* Wbase = W + bn;

    float acc[4][4][4];
#pragma unroll
    for (int mt = 0; mt < 4; mt++)
#pragma unroll
        for (int nt = 0; nt < 4; nt++)
#pragma unroll
            for (int r = 0; r < 4; r++) acc[mt][nt][r] = 0.f;

    g_load_chunk(Abase, Wbase, as_u, bs_u, tid);
    g_load_chunk(Abase + GBK, Wbase + (size_t)GBK * KD_,
                 as_u + ASLOT * 4, bs_u + BSLOT * 4, tid);

    for (int kc = 0; kc < GNC; kc++) {
        if (kc == GNC - 1) cpwait<0>(); else cpwait<1>();
        __syncthreads();

        const int kn = kc + 2;
        if (kn < GNC) {
            const int sl = kn % GST;
            g_load_chunk(Abase + kn * GBK, Wbase + (size_t)(kn * GBK) * KD_,
                         as_u + (uint32_t)sl * ASLOT * 4,
                         bs_u + (uint32_t)sl * BSLOT * 4, tid);
        }

        const float* Ac = As + (kc % GST) * ASLOT;
        const float* Bc = Bs + (kc % GST) * BSLOT;
#pragma unroll
        for (int ks = 0; ks < 4; ks++) {
            const int k0 = ks * 8;
            uint32_t af[4][4], bf[4][2];
#pragma unroll
            for (int mt = 0; mt < 4; mt++) {
                const int r0 = wm * 64 + mt * 16 + gid;
                af[mt][0] = __float_as_uint(Ac[r0 * ASTR + k0 + tig]);
                af[mt][1] = __float_as_uint(Ac[(r0 + 8) * ASTR + k0 + tig]);
                af[mt][2] = __float_as_uint(Ac[r0 * ASTR + k0 + tig + 4]);
                af[mt][3] = __float_as_uint(Ac[(r0 + 8) * ASTR + k0 + tig + 4]);
            }
#pragma unroll
            for (int nt = 0; nt < 4; nt++) {
                const int n0 = wn * 32 + nt * 8 + gid;
                bf[nt][0] = __float_as_uint(Bc[(k0 + tig) * BSTR + n0]);
                bf[nt][1] = __float_as_uint(Bc[(k0 + tig + 4) * BSTR + n0]);
            }
#pragma unroll
            for (int mt = 0; mt < 4; mt++)
#pragma unroll
                for (int nt = 0; nt < 4; nt++)
                    mma_tf32(acc[mt][nt], af[mt], bf[nt]);
        }
        __syncthreads();
    }

#pragma unroll
    for (int mt = 0; mt < 4; mt++) {
        const int r0 = bm + wm * 64 + mt * 16 + gid;
#pragma unroll
        for (int nt = 0; nt < 4; nt++) {
            const int col = bn + wn * 32 + nt * 8 + 2 * tig;
            const float b0 = bias[col], b1 = bias[col + 1];
            float2 v0 = make_float2(acc[mt][nt][0] + b0, acc[mt][nt][1] + b1);
            float2 v1 = make_float2(acc[mt][nt][2] + b0, acc[mt][nt][3] + b1);
            *(float2*)(C + (size_t)r0 * KD_ + col)       = v0;
            *(float2*)(C + (size_t)(r0 + 8) * KD_ + col) = v1;
        }
    }
}

// Fused Q/K/V projection: blockIdx.z selects weight/bias/output
__global__ __launch_bounds__(256, 2) void gemm_qkv(
    const float* __restrict__ bq, const float* __restrict__ bk,
    const float* __restrict__ bv)
{
    const float* W; const float* bias; float* C;
    if (blockIdx.z == 0)      { W = g_w[0]; bias = bq; C = g_q; }
    else if (blockIdx.z == 1) { W = g_w[1]; bias = bk; C = g_k; }
    else                      { W = g_w[2]; bias = bv; C = g_v; }
    gemm_body(g_x, W, bias, C, blockIdx.y * GBM, blockIdx.x * GBN);
}

__global__ __launch_bounds__(256, 2) void gemm_oproj(
    const float* __restrict__ bo, float* __restrict__ out)
{
    gemm_body(g_att, g_w[3], bo, out, blockIdx.y * GBM, blockIdx.x * GBN);
}

// ===========================================================================
// Flash attention, tf32 mma.sync. BQ=128, KV tiles of 64.
// Q frags in registers; K/V prefetched raw via cp.async, converted smem->smem.
// Output written tf32-pre-rounded (O-proj consumes it cvt-free).
// ===========================================================================
#define FBQ   128
#define FBK   64
#define FKSTR 68
#define FVSTR 72
#define FPSTR 68
#define OFF_PS   0
#define OFF_KS   (FBQ * FPSTR)
#define OFF_VS   (OFF_KS + FBK * FKSTR)
#define OFF_KRAW (OFF_VS + FBK * FVSTR)
#define OFF_VRAW (OFF_KRAW + FBK * 64)
#define FA_SMEMF (OFF_VRAW + FBK * 64)     // 25856 floats = 103424 B

__global__ __launch_bounds__(256, 2) void flash_attn_mma(
    const float* __restrict__ Q, const float* __restrict__ K,
    const float* __restrict__ V, float* __restrict__ O)
{
    extern __shared__ float sm[];
    float* Ps   = sm + OFF_PS;
    float* Ks   = sm + OFF_KS;
    float* Vs   = sm + OFF_VS;
    float* Kraw = sm + OFF_KRAW;
    float* Vraw = sm + OFF_VRAW;
    const uint32_t kraw_u = s2u(Kraw);
    const uint32_t vraw_u = s2u(Vraw);

    const int tid  = threadIdx.x;
    const int wid  = tid >> 5, lane = tid & 31;
    const int gid  = lane >> 2;
    const int tig  = lane & 3;
    const int qt   = (KS_ / FBQ - 1) - blockIdx.x;
    const int h    = blockIdx.y;
    const int b    = blockIdx.z;
    const int q0   = qt * FBQ;
    const int r0   = wid * 16 + gid;

    const float* Qb = Q + (size_t)b * KS_ * KD_ + (size_t)h * KHD_;
    const float* Kb = K + (size_t)b * KS_ * KD_ + (size_t)h * KHD_;
    const float* Vb = V + (size_t)b * KS_ * KD_ + (size_t)h * KHD_;

    const int ntiles = 2 * qt + 2;

    // Prefetch tile 0 raw K/V
#pragma unroll
    for (int i = 0; i < 4; i++) {
        int idx = tid + i * 256;
        int row = idx >> 4;
        int c4  = (idx & 15) * 4;
        cpa16(kraw_u + (uint32_t)idx * 16, Kb + (size_t)row * KD_ + c4);
        cpa16(vraw_u + (uint32_t)idx * 16, Vb + (size_t)row * KD_ + c4);
    }
    asm volatile("cp.async.commit_group;" ::: "memory");

    // Stage Q (scale 0.125*log2e folded), tf32-rounded, into Ps region
    const float qscale = 0.125f * 1.4426950408889634f;
#pragma unroll
    for (int i = 0; i < 8; i++) {
        int idx = tid + i * 256;
        int row = idx >> 4;
        int c4  = (idx & 15) * 4;
        float4 v4 = *(const float4*)(Qb + (size_t)(q0 + row) * KD_ + c4);
        uint4 u;
        u.x = f2tf32(v4.x * qscale);
        u.y = f2tf32(v4.y * qscale);
        u.z = f2tf32(v4.z * qscale);
        u.w = f2tf32(v4.w * qscale);
        *(uint4*)(Ps + row * FPSTR + c4) = u;
    }
    __syncthreads();

    uint32_t qf[8][4];
#pragma unroll
    for (int k8 = 0; k8 < 8; k8++) {
        qf[k8][0] = __float_as_uint(Ps[r0 * FPSTR + k8 * 8 + tig]);
        qf[k8][1] = __float_as_uint(Ps[(r0 + 8) * FPSTR + k8 * 8 + tig]);
        qf[k8][2] = __float_as_uint(Ps[r0 * FPSTR + k8 * 8 + tig + 4]);
        qf[k8][3] = __float_as_uint(Ps[(r0 + 8) * FPSTR + k8 * 8 + tig + 4]);
    }

    // Convert tile 0 raw -> Ks/Vs
    cpwait<0>();
    __syncthreads();
#pragma unroll
    for (int i = 0; i < 4; i++) {
        int idx = tid + i * 256;
        int row = idx >> 4;
        int c4  = (idx & 15) * 4;
        float4 kr = *(const float4*)(Kraw + row * 64 + c4);
        uint4 uk;
        uk.x = f2tf32(kr.x); uk.y = f2tf32(kr.y);
        uk.z = f2tf32(kr.z); uk.w = f2tf32(kr.w);
        *(uint4*)(Ks + row * FKSTR + c4) = uk;
        float4 vr = *(const float4*)(Vraw + row * 64 + c4);
        uint4 uv;
        uv.x = f2tf32(vr.x); uv.y = f2tf32(vr.y);
        uv.z = f2tf32(vr.z); uv.w = f2tf32(vr.w);
        *(uint4*)(Vs + row * FVSTR + c4) = uv;
    }
    __syncthreads();

    float oacc[8][4];
#pragma unroll
    for (int f = 0; f < 8; f++)
#pragma unroll
        for (int r = 0; r < 4; r++) oacc[f][r] = 0.f;
    float mstate[2] = {-1e30f, -1e30f};
    float lstate[2] = {0.f, 0.f};

    for (int kt = 0; kt < ntiles; kt++) {
        if (kt + 1 < ntiles) {
            const int kn0 = (kt + 1) * FBK;
#pragma unroll
            for (int i = 0; i < 4; i++) {
                int idx = tid + i * 256;
                int row = idx >> 4;
                int c4  = (idx & 15) * 4;
                cpa16(kraw_u + (uint32_t)idx * 16, Kb + (size_t)(kn0 + row) * KD_ + c4);
                cpa16(vraw_u + (uint32_t)idx * 16, Vb + (size_t)(kn0 + row) * KD_ + c4);
            }
            asm volatile("cp.async.commit_group;" ::: "memory");
        }

        float sacc[8][4];
#pragma unroll
        for (int f = 0; f < 8; f++)
#pragma unroll
            for (int r = 0; r < 4; r++) sacc[f][r] = 0.f;
#pragma unroll
        for (int k8 = 0; k8 < 8; k8++) {
#pragma unroll
            for (int f = 0; f < 8; f++) {
                uint32_t bb[2];
                bb[0] = __float_as_uint(Ks[(f * 8 + gid) * FKSTR + k8 * 8 + tig]);
                bb[1] = __float_as_uint(Ks[(f * 8 + gid) * FKSTR + k8 * 8 + tig + 4]);
                mma_tf32(sacc[f], qf[k8], bb);
            }
        }

        if (kt >= 2 * qt) {
            const int k0g = kt * FBK;
            const int qrow0 = q0 + wid * 16 + gid;
#pragma unroll
            for (int f = 0; f < 8; f++) {
                const int kc = k0g + f * 8 + 2 * tig;
                if (kc     > qrow0)     sacc[f][0] = -1e30f;
                if (kc + 1 > qrow0)     sacc[f][1] = -1e30f;
                if (kc     > qrow0 + 8) sacc[f][2] = -1e30f;
                if (kc + 1 > qrow0 + 8) sacc[f][3] = -1e30f;
            }
        }

        float mx0 = -1e30f, mx1 = -1e30f;
#pragma unroll
        for (int f = 0; f < 8; f++) {
            mx0 = fmaxf(mx0, fmaxf(sacc[f][0], sacc[f][1]));
            mx1 = fmaxf(mx1, fmaxf(sacc[f][2], sacc[f][3]));
        }
        mx0 = fmaxf(mx0, __shfl_xor_sync(0xFFFFFFFF, mx0, 1));
        mx0 = fmaxf(mx0, __shfl_xor_sync(0xFFFFFFFF, mx0, 2));
        mx1 = fmaxf(mx1, __shfl_xor_sync(0xFFFFFFFF, mx1, 1));
        mx1 = fmaxf(mx1, __shfl_xor_sync(0xFFFFFFFF, mx1, 2));

        const float mnew0 = fmaxf(mstate[0], mx0);
        const float mnew1 = fmaxf(mstate[1], mx1);
        const float fac0 = ex2(mstate[0] - mnew0);
        const float fac1 = ex2(mstate[1] - mnew1);
        mstate[0] = mnew0; mstate[1] = mnew1;

        float ls0 = 0.f, ls1 = 0.f;
#pragma unroll
        for (int f = 0; f < 8; f++) {
            float p0 = ex2(sacc[f][0] - mnew0);
            float p1 = ex2(sacc[f][1] - mnew0);
            float p2 = ex2(sacc[f][2] - mnew1);
            float p3 = ex2(sacc[f][3] - mnew1);
            ls0 += p0 + p1;
            ls1 += p2 + p3;
            uint2 w0 = make_uint2(f2tf32(p0), f2tf32(p1));
            uint2 w1 = make_uint2(f2tf32(p2), f2tf32(p3));
            *(uint2*)(Ps + r0 * FPSTR + f * 8 + 2 * tig)       = w0;
            *(uint2*)(Ps + (r0 + 8) * FPSTR + f * 8 + 2 * tig) = w1;
        }
        ls0 += __shfl_xor_sync(0xFFFFFFFF, ls0, 1);
        ls0 += __shfl_xor_sync(0xFFFFFFFF, ls0, 2);
        ls1 += __shfl_xor_sync(0xFFFFFFFF, ls1, 1);
        ls1 += __shfl_xor_sync(0xFFFFFFFF, ls1, 2);
        lstate[0] = lstate[0] * fac0 + ls0;
        lstate[1] = lstate[1] * fac1 + ls1;

#pragma unroll
        for (int f = 0; f < 8; f++) {
            oacc[f][0] *= fac0; oacc[f][1] *= fac0;
            oacc[f][2] *= fac1; oacc[f][3] *= fac1;
        }
        __syncwarp();

#pragma unroll
        for (int k8 = 0; k8 < 8; k8++) {
            uint32_t a[4];
            a[0] = __float_as_uint(Ps[r0 * FPSTR + k8 * 8 + tig]);
            a[1] = __float_as_uint(Ps[(r0 + 8) * FPSTR + k8 * 8 + tig]);
            a[2] = __float_as_uint(Ps[r0 * FPSTR + k8 * 8 + tig + 4]);
            a[3] = __float_as_uint(Ps[(r0 + 8) * FPSTR + k8 * 8 + tig + 4]);
#pragma unroll
            for (int f = 0; f < 8; f++) {
                uint32_t bb[2];
                bb[0] = __float_as_uint(Vs[(k8 * 8 + tig) * FVSTR + f * 8 + gid]);
                bb[1] = __float_as_uint(Vs[(k8 * 8 + tig + 4) * FVSTR + f * 8 + gid]);
                mma_tf32(oacc[f], a, bb);
            }
        }

        if (kt + 1 < ntiles) {
            cpwait<0>();
            __syncthreads();
#pragma unroll
            for (int i = 0; i < 4; i++) {
                int idx = tid + i * 256;
                int row = idx >> 4;
                int c4  = (idx & 15) * 4;
                float4 kr = *(const float4*)(Kraw + row * 64 + c4);
                uint4 uk;
                uk.x = f2tf32(kr.x); uk.y = f2tf32(kr.y);
                uk.z = f2tf32(kr.z); uk.w = f2tf32(kr.w);
                *(uint4*)(Ks + row * FKSTR + c4) = uk;
                float4 vr = *(const float4*)(Vraw + row * 64 + c4);
                uint4 uv;
                uv.x = f2tf32(vr.x); uv.y = f2tf32(vr.y);
                uv.z = f2tf32(vr.z); uv.w = f2tf32(vr.w);
                *(uint4*)(Vs + row * FVSTR + c4) = uv;
            }
            __syncthreads();
        }
    }

    // Normalize + write out tf32-pre-rounded (O-proj consumes cvt-free)
    const float inv0 = 1.f / lstate[0];
    const float inv1 = 1.f / lstate[1];
    float* Ob = O + (size_t)b * KS_ * KD_ + (size_t)h * KHD_;
    const int qrow0 = q0 + wid * 16 + gid;
#pragma unroll
    for (int f = 0; f < 8; f++) {
        const int col = f * 8 + 2 * tig;
        uint2 v0 = make_uint2(f2tf32(oacc[f][0] * inv0), f2tf32(oacc[f][1] * inv0));
        uint2 v1 = make_uint2(f2tf32(oacc[f][2] * inv1), f2tf32(oacc[f][3] * inv1));
        *(uint2*)(Ob + (size_t)qrow0 * KD_ + col)       = v0;
        *(uint2*)(Ob + (size_t)(qrow0 + 8) * KD_ + col) = v1;
    }
}

// ---------------------------------------------------------------------------
// Launch
// ---------------------------------------------------------------------------
extern "C" void kernel_launch(void* const* d_in, const int* in_sizes, int n_in,
                              void* d_out, int out_size)
{
    (void)in_sizes; (void)n_in; (void)out_size;
    const float* x  = (const float*)d_in[0];
    const float* Wq = (const float*)d_in[1];
    const float* bq = (const float*)d_in[2];
    const float* Wk = (const float*)d_in[3];
    const float* bk = (const float*)d_in[4];
    const float* Wv = (const float*)d_in[5];
    const float* bv = (const float*)d_in[6];
    const float* Wo = (const float*)d_in[7];
    const float* bo = (const float*)d_in[8];
    float* out = (float*)d_out;

    float *q, *k, *v, *att;
    cudaGetSymbolAddress((void**)&q,   g_q);
    cudaGetSymbolAddress((void**)&k,   g_k);
    cudaGetSymbolAddress((void**)&v,   g_v);
    cudaGetSymbolAddress((void**)&att, g_att);

    const int gemm_smem = GST * (ASLOT + BSLOT) * (int)sizeof(float);
    cudaFuncSetAttribute(gemm_qkv,   cudaFuncAttributeMaxDynamicSharedMemorySize, gemm_smem);
    cudaFuncSetAttribute(gemm_oproj, cudaFuncAttributeMaxDynamicSharedMemorySize, gemm_smem);

    const int fa_smem = FA_SMEMF * (int)sizeof(float);   // 103,424 B
    cudaFuncSetAttribute(flash_attn_mma, cudaFuncAttributeMaxDynamicSharedMemorySize, fa_smem);

    // Pre-round x + weights to tf32
    dim3 rGrid(128, 1, 5);
    round_tf32_all<<<rGrid, 256>>>(x, Wq, Wk, Wv, Wo);

    dim3 gGridQKV(KD_ / GBN, KM_ / GBM, 3);  // (8, 32, 3)
    gemm_qkv<<<gGridQKV, 256, gemm_smem>>>(bq, bk, bv);

    dim3 faGrid(KS_ / FBQ, KH_, KB_);        // (16, 16, 2)
    flash_attn_mma<<<faGrid, 256, fa_smem>>>(q, k, v, att);

    dim3 gGrid(KD_ / GBN, KM_ / GBM);        // (8, 32)
    gemm_oproj<<<gGrid, 256, gemm_smem>>>(bo, out);
}

// round 8
// speedup vs baseline: 3.4279x; 1.0579x over previous
#include <cuda_runtime.h>
#include <cstdint>

// Problem constants
#define KB_  2
#define KS_  2048
#define KD_  1024
#define KH_  16
#define KHD_ 64
#define KM_  (KB_ * KS_)   // 4096 rows

// Scratch (allocation-free rule: __device__ globals)
__device__ float g_q[(size_t)KM_ * KD_];
__device__ float g_k[(size_t)KM_ * KD_];
__device__ float g_v[(size_t)KM_ * KD_];
__device__ float g_att[(size_t)KM_ * KD_];
__device__ float g_x[(size_t)KM_ * KD_];        // tf32-rounded x
__device__ float g_w[4][(size_t)KD_ * KD_];     // tf32-rounded weights

// ===========================================================================
// Helpers
// ===========================================================================
__device__ __forceinline__ void cpa16(uint32_t dst, const float* src) {
    asm volatile("cp.async.cg.shared.global [%0], [%1], 16;"
                 :: "r"(dst), "l"(src));
}
template <int N>
__device__ __forceinline__ void cpwait() {
    asm volatile("cp.async.wait_group %0;" :: "n"(N) : "memory");
}
__device__ __forceinline__ uint32_t s2u(const void* p) {
    uint32_t a;
    asm("{ .reg .u64 t; cvta.to.shared.u64 t, %1; cvt.u32.u64 %0, t; }"
        : "=r"(a) : "l"(p));
    return a;
}
__device__ __forceinline__ uint32_t f2tf32(float f) {
    uint32_t u;
    asm("cvt.rna.tf32.f32 %0, %1;" : "=r"(u) : "f"(f));
    return u;
}
__device__ __forceinline__ float ex2(float x) {
    float y;
    asm("ex2.approx.f32 %0, %1;" : "=f"(y) : "f"(x));
    return y;
}
// D += A(16x8) * B(8x8), tf32 inputs, fp32 accumulate
__device__ __forceinline__ void mma_tf32(float* c, const uint32_t* a, const uint32_t* b) {
    asm volatile(
        "mma.sync.aligned.m16n8k8.row.col.f32.tf32.tf32.f32 "
        "{%0,%1,%2,%3}, {%4,%5,%6,%7}, {%8,%9}, {%0,%1,%2,%3};"
        : "+f"(c[0]), "+f"(c[1]), "+f"(c[2]), "+f"(c[3])
        : "r"(a[0]), "r"(a[1]), "r"(a[2]), "r"(a[3]), "r"(b[0]), "r"(b[1]));
}

#define QSCALE (0.125f * 1.4426950408889634f)   // 1/sqrt(64) * log2(e)

// ===========================================================================
// Pre-round x + 4 weights to tf32 (rna), once per launch.
// ===========================================================================
__global__ __launch_bounds__(256) void round_tf32_all(
    const float* __restrict__ x,
    const float* __restrict__ Wq, const float* __restrict__ Wk,
    const float* __restrict__ Wv, const float* __restrict__ Wo)
{
    const int z = blockIdx.z;
    const float* src;
    float* dst;
    size_t n4;
    if (z == 0) { src = x;  dst = g_x;    n4 = (size_t)KM_ * KD_ / 4; }
    else {
        src = (z == 1) ? Wq : (z == 2) ? Wk : (z == 3) ? Wv : Wo;
        dst = g_w[z - 1];
        n4  = (size_t)KD_ * KD_ / 4;
    }
    const size_t stride = (size_t)gridDim.x * 256;
    for (size_t i = blockIdx.x * 256 + threadIdx.x; i < n4; i += stride) {
        float4 v = *(const float4*)(src + i * 4);
        uint4 u;
        u.x = f2tf32(v.x); u.y = f2tf32(v.y);
        u.z = f2tf32(v.z); u.w = f2tf32(v.w);
        *(uint4*)(dst + i * 4) = u;
    }
}

// ===========================================================================
// tf32 mma.sync GEMM core — inputs pre-rounded, no cvt in inner loop.
// Epilogue: C = (acc + bias) * outscale, optionally tf32-rounded.
// ===========================================================================
#define GBM 128
#define GBN 128
#define GBK 32
#define GST 3
#define GNC (KD_ / GBK)
#define ASTR 36
#define BSTR 136
#define ASLOT (GBM * ASTR)
#define BSLOT (GBK * BSTR)

__device__ __forceinline__ void g_load_chunk(
    const float* __restrict__ Ag, const float* __restrict__ Wg,
    uint32_t as, uint32_t bs, int tid)
{
#pragma unroll
    for (int i = 0; i < 4; i++) {
        int idx = tid + i * 256;
        int r = idx >> 3, c4 = (idx & 7) * 4;
        cpa16(as + (uint32_t)(r * ASTR + c4) * 4, Ag + (size_t)r * KD_ + c4);
    }
#pragma unroll
    for (int i = 0; i < 4; i++) {
        int idx = tid + i * 256;
        int r = idx >> 5, c4 = (idx & 31) * 4;
        cpa16(bs + (uint32_t)(r * BSTR + c4) * 4, Wg + (size_t)r * KD_ + c4);
    }
    asm volatile("cp.async.commit_group;" ::: "memory");
}

__device__ __forceinline__ void gemm_body(
    const float* __restrict__ A, const float* __restrict__ W,
    const float* __restrict__ bias, float* __restrict__ C,
    int bm, int bn, float outscale, bool roundout)
{
    extern __shared__ float smem[];
    float* As = smem;
    float* Bs = smem + GST * ASLOT;
    const uint32_t as_u = s2u(As);
    const uint32_t bs_u = s2u(Bs);

    const int tid  = threadIdx.x;
    const int wid  = tid >> 5, lane = tid & 31;
    const int wm   = wid >> 2;
    const int wn   = wid & 3;
    const int gid  = lane >> 2;
    const int tig  = lane & 3;

    const float* Abase = A + (size_t)bm * KD_;
    const float* Wbase = W + bn;

    float acc[4][4][4];
#pragma unroll
    for (int mt = 0; mt < 4; mt++)
#pragma unroll
        for (int nt = 0; nt < 4; nt++)
#pragma unroll
            for (int r = 0; r < 4; r++) acc[mt][nt][r] = 0.f;

    g_load_chunk(Abase, Wbase, as_u, bs_u, tid);
    g_load_chunk(Abase + GBK, Wbase + (size_t)GBK * KD_,
                 as_u + ASLOT * 4, bs_u + BSLOT * 4, tid);

    for (int kc = 0; kc < GNC; kc++) {
        if (kc == GNC - 1) cpwait<0>(); else cpwait<1>();
        __syncthreads();

        const int kn = kc + 2;
        if (kn < GNC) {
            const int sl = kn % GST;
            g_load_chunk(Abase + kn * GBK, Wbase + (size_t)(kn * GBK) * KD_,
                         as_u + (uint32_t)sl * ASLOT * 4,
                         bs_u + (uint32_t)sl * BSLOT * 4, tid);
        }

        const float* Ac = As + (kc % GST) * ASLOT;
        const float* Bc = Bs + (kc % GST) * BSLOT;
#pragma unroll
        for (int ks = 0; ks < 4; ks++) {
            const int k0 = ks * 8;
            uint32_t af[4][4], bf[4][2];
#pragma unroll
            for (int mt = 0; mt < 4; mt++) {
                const int r0 = wm * 64 + mt * 16 + gid;
                af[mt][0] = __float_as_uint(Ac[r0 * ASTR + k0 + tig]);
                af[mt][1] = __float_as_uint(Ac[(r0 + 8) * ASTR + k0 + tig]);
                af[mt][2] = __float_as_uint(Ac[r0 * ASTR + k0 + tig + 4]);
                af[mt][3] = __float_as_uint(Ac[(r0 + 8) * ASTR + k0 + tig + 4]);
            }
#pragma unroll
            for (int nt = 0; nt < 4; nt++) {
                const int n0 = wn * 32 + nt * 8 + gid;
                bf[nt][0] = __float_as_uint(Bc[(k0 + tig) * BSTR + n0]);
                bf[nt][1] = __float_as_uint(Bc[(k0 + tig + 4) * BSTR + n0]);
            }
#pragma unroll
            for (int mt = 0; mt < 4; mt++)
#pragma unroll
                for (int nt = 0; nt < 4; nt++)
                    mma_tf32(acc[mt][nt], af[mt], bf[nt]);
        }
        __syncthreads();
    }

#pragma unroll
    for (int mt = 0; mt < 4; mt++) {
        const int r0 = bm + wm * 64 + mt * 16 + gid;
#pragma unroll
        for (int nt = 0; nt < 4; nt++) {
            const int col = bn + wn * 32 + nt * 8 + 2 * tig;
            const float b0 = bias[col], b1 = bias[col + 1];
            float e0 = (acc[mt][nt][0] + b0) * outscale;
            float e1 = (acc[mt][nt][1] + b1) * outscale;
            float e2 = (acc[mt][nt][2] + b0) * outscale;
            float e3 = (acc[mt][nt][3] + b1) * outscale;
            if (roundout) {
                e0 = __uint_as_float(f2tf32(e0));
                e1 = __uint_as_float(f2tf32(e1));
                e2 = __uint_as_float(f2tf32(e2));
                e3 = __uint_as_float(f2tf32(e3));
            }
            *(float2*)(C + (size_t)r0 * KD_ + col)       = make_float2(e0, e1);
            *(float2*)(C + (size_t)(r0 + 8) * KD_ + col) = make_float2(e2, e3);
        }
    }
}

// Fused Q/K/V projection; outputs tf32-pre-rounded; Q pre-scaled by QSCALE.
__global__ __launch_bounds__(256, 2) void gemm_qkv(
    const float* __restrict__ bq, const float* __restrict__ bk,
    const float* __restrict__ bv)
{
    const float* W; const float* bias; float* C; float sc;
    if (blockIdx.z == 0)      { W = g_w[0]; bias = bq; C = g_q; sc = QSCALE; }
    else if (blockIdx.z == 1) { W = g_w[1]; bias = bk; C = g_k; sc = 1.f; }
    else                      { W = g_w[2]; bias = bv; C = g_v; sc = 1.f; }
    gemm_body(g_x, W, bias, C, blockIdx.y * GBM, blockIdx.x * GBN, sc, true);
}

__global__ __launch_bounds__(256, 2) void gemm_oproj(
    const float* __restrict__ bo, float* __restrict__ out)
{
    gemm_body(g_att, g_w[3], bo, out, blockIdx.y * GBM, blockIdx.x * GBN, 1.f, false);
}

// ===========================================================================
// Flash attention, tf32 mma.sync. BQ=128, KV tiles of 64.
// Q/K/V arrive pre-rounded (and Q pre-scaled) from the QKV GEMM, so K/V
// cp.async lands DIRECTLY in the double-buffered MMA tiles — no convert pass.
// One __syncthreads per KV tile. Output written tf32-pre-rounded.
// ===========================================================================
#define FBQ   128
#define FBK   64
#define FKSTR 68
#define FVSTR 72
#define FPSTR 68
#define OFF_PS 0
#define OFF_K0 (FBQ * FPSTR)                   // 2 stages of [64][68]
#define OFF_V0 (OFF_K0 + 2 * FBK * FKSTR)      // 2 stages of [64][72]
#define KSTG   (FBK * FKSTR)
#define VSTG   (FBK * FVSTR)
#define FA_SMEMF (OFF_V0 + 2 * VSTG)           // 26624 floats = 106496 B

__global__ __launch_bounds__(256, 2) void flash_attn_mma(
    const float* __restrict__ Q, const float* __restrict__ K,
    const float* __restrict__ V, float* __restrict__ O)
{
    extern __shared__ float sm[];
    float* Ps = sm + OFF_PS;
    const uint32_t k_u = s2u(sm + OFF_K0);
    const uint32_t v_u = s2u(sm + OFF_V0);

    const int tid  = threadIdx.x;
    const int wid  = tid >> 5, lane = tid & 31;
    const int gid  = lane >> 2;
    const int tig  = lane & 3;
    const int qt   = (KS_ / FBQ - 1) - blockIdx.x;   // heavy tiles first
    const int h    = blockIdx.y;
    const int b    = blockIdx.z;
    const int q0   = qt * FBQ;
    const int r0   = wid * 16 + gid;

    const float* Qb = Q + (size_t)b * KS_ * KD_ + (size_t)h * KHD_;
    const float* Kb = K + (size_t)b * KS_ * KD_ + (size_t)h * KHD_;
    const float* Vb = V + (size_t)b * KS_ * KD_ + (size_t)h * KHD_;

    const int ntiles = 2 * qt + 2;

    // Prefetch tile 0 directly into stage 0 (data already tf32-rounded)
#pragma unroll
    for (int i = 0; i < 4; i++) {
        int idx = tid + i * 256;
        int row = idx >> 4;
        int c4  = (idx & 15) * 4;
        cpa16(k_u + (uint32_t)(row * FKSTR + c4) * 4, Kb + (size_t)row * KD_ + c4);
        cpa16(v_u + (uint32_t)(row * FVSTR + c4) * 4, Vb + (size_t)row * KD_ + c4);
    }
    asm volatile("cp.async.commit_group;" ::: "memory");

    // Stage Q (already scaled + rounded) into Ps region — plain copy
#pragma unroll
    for (int i = 0; i < 8; i++) {
        int idx = tid + i * 256;
        int row = idx >> 4;
        int c4  = (idx & 15) * 4;
        *(float4*)(Ps + row * FPSTR + c4) =
            *(const float4*)(Qb + (size_t)(q0 + row) * KD_ + c4);
    }
    __syncthreads();

    // Hoist Q fragments to registers
    uint32_t qf[8][4];
#pragma unroll
    for (int k8 = 0; k8 < 8; k8++) {
        qf[k8][0] = __float_as_uint(Ps[r0 * FPSTR + k8 * 8 + tig]);
        qf[k8][1] = __float_as_uint(Ps[(r0 + 8) * FPSTR + k8 * 8 + tig]);
        qf[k8][2] = __float_as_uint(Ps[r0 * FPSTR + k8 * 8 + tig + 4]);
        qf[k8][3] = __float_as_uint(Ps[(r0 + 8) * FPSTR + k8 * 8 + tig + 4]);
    }

    cpwait<0>();
    __syncthreads();   // tile 0 ready; all warps past qf reads (Ps reused for P)

    float oacc[8][4];
#pragma unroll
    for (int f = 0; f < 8; f++)
#pragma unroll
        for (int r = 0; r < 4; r++) oacc[f][r] = 0.f;
    float mstate[2] = {-1e30f, -1e30f};
    float lstate[2] = {0.f, 0.f};

    for (int kt = 0; kt < ntiles; kt++) {
        const int st = kt & 1;
        // Prefetch tile kt+1 into the other stage (freed by last iteration's bar)
        if (kt + 1 < ntiles) {
            const int kn0 = (kt + 1) * FBK;
            const uint32_t ku = k_u + (uint32_t)(st ^ 1) * KSTG * 4;
            const uint32_t vu = v_u + (uint32_t)(st ^ 1) * VSTG * 4;
#pragma unroll
            for (int i = 0; i < 4; i++) {
                int idx = tid + i * 256;
                int row = idx >> 4;
                int c4  = (idx & 15) * 4;
                cpa16(ku + (uint32_t)(row * FKSTR + c4) * 4,
                      Kb + (size_t)(kn0 + row) * KD_ + c4);
                cpa16(vu + (uint32_t)(row * FVSTR + c4) * 4,
                      Vb + (size_t)(kn0 + row) * KD_ + c4);
            }
            asm volatile("cp.async.commit_group;" ::: "memory");
        }

        const float* Ks = sm + OFF_K0 + st * KSTG;
        const float* Vs = sm + OFF_V0 + st * VSTG;

        // S = Q K^T
        float sacc[8][4];
#pragma unroll
        for (int f = 0; f < 8; f++)
#pragma unroll
            for (int r = 0; r < 4; r++) sacc[f][r] = 0.f;
#pragma unroll
        for (int k8 = 0; k8 < 8; k8++) {
#pragma unroll
            for (int f = 0; f < 8; f++) {
                uint32_t bb[2];
                bb[0] = __float_as_uint(Ks[(f * 8 + gid) * FKSTR + k8 * 8 + tig]);
                bb[1] = __float_as_uint(Ks[(f * 8 + gid) * FKSTR + k8 * 8 + tig + 4]);
                mma_tf32(sacc[f], qf[k8], bb);
            }
        }

        // Causal mask (last two tiles only)
        if (kt >= 2 * qt) {
            const int k0g = kt * FBK;
            const int qrow0 = q0 + wid * 16 + gid;
#pragma unroll
            for (int f = 0; f < 8; f++) {
                const int kc = k0g + f * 8 + 2 * tig;
                if (kc     > qrow0)     sacc[f][0] = -1e30f;
                if (kc + 1 > qrow0)     sacc[f][1] = -1e30f;
                if (kc     > qrow0 + 8) sacc[f][2] = -1e30f;
                if (kc + 1 > qrow0 + 8) sacc[f][3] = -1e30f;
            }
        }

        // Row max over tig group
        float mx0 = -1e30f, mx1 = -1e30f;
#pragma unroll
        for (int f = 0; f < 8; f++) {
            mx0 = fmaxf(mx0, fmaxf(sacc[f][0], sacc[f][1]));
            mx1 = fmaxf(mx1, fmaxf(sacc[f][2], sacc[f][3]));
        }
        mx0 = fmaxf(mx0, __shfl_xor_sync(0xFFFFFFFF, mx0, 1));
        mx0 = fmaxf(mx0, __shfl_xor_sync(0xFFFFFFFF, mx0, 2));
        mx1 = fmaxf(mx1, __shfl_xor_sync(0xFFFFFFFF, mx1, 1));
        mx1 = fmaxf(mx1, __shfl_xor_sync(0xFFFFFFFF, mx1, 2));

        const float mnew0 = fmaxf(mstate[0], mx0);
        const float mnew1 = fmaxf(mstate[1], mx1);
        const float fac0 = ex2(mstate[0] - mnew0);
        const float fac1 = ex2(mstate[1] - mnew1);
        mstate[0] = mnew0; mstate[1] = mnew1;

        // P = 2^(S - m), row sums, store tf32 P (warp-private rows)
        float ls0 = 0.f, ls1 = 0.f;
#pragma unroll
        for (int f = 0; f < 8; f++) {
            float p0 = ex2(sacc[f][0] - mnew0);
            float p1 = ex2(sacc[f][1] - mnew0);
            float p2 = ex2(sacc[f][2] - mnew1);
            float p3 = ex2(sacc[f][3] - mnew1);
            ls0 += p0 + p1;
            ls1 += p2 + p3;
            uint2 w0 = make_uint2(f2tf32(p0), f2tf32(p1));
            uint2 w1 = make_uint2(f2tf32(p2), f2tf32(p3));
            *(uint2*)(Ps + r0 * FPSTR + f * 8 + 2 * tig)       = w0;
            *(uint2*)(Ps + (r0 + 8) * FPSTR + f * 8 + 2 * tig) = w1;
        }
        ls0 += __shfl_xor_sync(0xFFFFFFFF, ls0, 1);
        ls0 += __shfl_xor_sync(0xFFFFFFFF, ls0, 2);
        ls1 += __shfl_xor_sync(0xFFFFFFFF, ls1, 1);
        ls1 += __shfl_xor_sync(0xFFFFFFFF, ls1, 2);
        lstate[0] = lstate[0] * fac0 + ls0;
        lstate[1] = lstate[1] * fac1 + ls1;

#pragma unroll
        for (int f = 0; f < 8; f++) {
            oacc[f][0] *= fac0; oacc[f][1] *= fac0;
            oacc[f][2] *= fac1; oacc[f][3] *= fac1;
        }
        __syncwarp();

        // O += P V
#pragma unroll
        for (int k8 = 0; k8 < 8; k8++) {
            uint32_t a[4];
            a[0] = __float_as_uint(Ps[r0 * FPSTR + k8 * 8 + tig]);
            a[1] = __float_as_uint(Ps[(r0 + 8) * FPSTR + k8 * 8 + tig]);
            a[2] = __float_as_uint(Ps[r0 * FPSTR + k8 * 8 + tig + 4]);
            a[3] = __float_as_uint(Ps[(r0 + 8) * FPSTR + k8 * 8 + tig + 4]);
#pragma unroll
            for (int f = 0; f < 8; f++) {
                uint32_t bb[2];
                bb[0] = __float_as_uint(Vs[(k8 * 8 + tig) * FVSTR + f * 8 + gid]);
                bb[1] = __float_as_uint(Vs[(k8 * 8 + tig + 4) * FVSTR + f * 8 + gid]);
                mma_tf32(oacc[f], a, bb);
            }
        }

        // Wait for tile kt+1 data; release this stage for tile kt+2
        if (kt + 1 < ntiles) {
            cpwait<0>();
            __syncthreads();
        }
    }

    // Normalize + write out tf32-pre-rounded (O-proj consumes cvt-free)
    const float inv0 = 1.f / lstate[0];
    const float inv1 = 1.f / lstate[1];
    float* Ob = O + (size_t)b * KS_ * KD_ + (size_t)h * KHD_;
    const int qrow0 = q0 + wid * 16 + gid;
#pragma unroll
    for (int f = 0; f < 8; f++) {
        const int col = f * 8 + 2 * tig;
        uint2 v0 = make_uint2(f2tf32(oacc[f][0] * inv0), f2tf32(oacc[f][1] * inv0));
        uint2 v1 = make_uint2(f2tf32(oacc[f][2] * inv1), f2tf32(oacc[f][3] * inv1));
        *(uint2*)(Ob + (size_t)qrow0 * KD_ + col)       = v0;
        *(uint2*)(Ob + (size_t)(qrow0 + 8) * KD_ + col) = v1;
    }
}

// ---------------------------------------------------------------------------
// Launch
// ---------------------------------------------------------------------------
extern "C" void kernel_launch(void* const* d_in, const int* in_sizes, int n_in,
                              void* d_out, int out_size)
{
    (void)in_sizes; (void)n_in; (void)out_size;
    const float* x  = (const float*)d_in[0];
    const float* Wq = (const float*)d_in[1];
    const float* bq = (const float*)d_in[2];
    const float* Wk = (const float*)d_in[3];
    const float* bk = (const float*)d_in[4];
    const float* Wv = (const float*)d_in[5];
    const float* bv = (const float*)d_in[6];
    const float* Wo = (const float*)d_in[7];
    const float* bo = (const float*)d_in[8];
    float* out = (float*)d_out;

    float *q, *k, *v, *att;
    cudaGetSymbolAddress((void**)&q,   g_q);
    cudaGetSymbolAddress((void**)&k,   g_k);
    cudaGetSymbolAddress((void**)&v,   g_v);
    cudaGetSymbolAddress((void**)&att, g_att);

    const int gemm_smem = GST * (ASLOT + BSLOT) * (int)sizeof(float);
    cudaFuncSetAttribute(gemm_qkv,   cudaFuncAttributeMaxDynamicSharedMemorySize, gemm_smem);
    cudaFuncSetAttribute(gemm_oproj, cudaFuncAttributeMaxDynamicSharedMemorySize, gemm_smem);

    const int fa_smem = FA_SMEMF * (int)sizeof(float);   // 106,496 B
    cudaFuncSetAttribute(flash_attn_mma, cudaFuncAttributeMaxDynamicSharedMemorySize, fa_smem);

    // Pre-round x + weights to tf32
    dim3 rGrid(128, 1, 5);
    round_tf32_all<<<rGrid, 256>>>(x, Wq, Wk, Wv, Wo);

    dim3 gGridQKV(KD_ / GBN, KM_ / GBM, 3);  // (8, 32, 3)
    gemm_qkv<<<gGridQKV, 256, gemm_smem>>>(bq, bk, bv);

    dim3 faGrid(KS_ / FBQ, KH_, KB_);        // (16, 16, 2)
    flash_attn_mma<<<faGrid, 256, fa_smem>>>(q, k, v, att);

    dim3 gGrid(KD_ / GBN, KM_ / GBM);        // (8, 32)
    gemm_oproj<<<gGrid, 256, gemm_smem>>>(bo, out);
}